// round 6
// baseline (speedup 1.0000x reference)
#include <cuda_runtime.h>
#include <cuda_bf16.h>
#include <cstdint>
#include <cstddef>

#define BATCH 8
#define CDIM 256
#define HW 4096
#define TDIM 1024

// ---------------------------------------------------------------------------
// Static scratch (allocation forbidden)
// ---------------------------------------------------------------------------
__device__ float g_bufA[(size_t)BATCH * CDIM * HW];
__device__ float g_bufB[(size_t)BATCH * CDIM * HW];
__device__ float g_qkv [(size_t)BATCH * 3 * CDIM * HW];
__device__ float g_temb[BATCH * CDIM];
__device__ __nv_bfloat16 g_qT [(size_t)BATCH * HW * CDIM];
__device__ __nv_bfloat16 g_kT [(size_t)BATCH * HW * CDIM];
__device__ __nv_bfloat16 g_vbf[(size_t)BATCH * CDIM * HW];
__device__ float g_w1r[CDIM * CDIM * 9];
__device__ float g_w2r[CDIM * CDIM * 9];
__device__ float g_wqr[3 * CDIM * CDIM];
__device__ float g_wor[CDIM * CDIM];

// ---------------------------------------------------------------------------
// PTX helpers
// ---------------------------------------------------------------------------
__device__ __forceinline__ uint32_t smem_u32(const void* p) {
    uint32_t a;
    asm("{ .reg .u64 t; cvta.to.shared.u64 t, %1; cvt.u32.u64 %0, t; }"
        : "=r"(a) : "l"(p));
    return a;
}
__device__ __forceinline__ void cp16(uint32_t dst, const void* src) {
    asm volatile("cp.async.cg.shared.global [%0], [%1], 16;" :: "r"(dst), "l"(src));
}
__device__ __forceinline__ void cp4_pred(uint32_t dst, const void* src, bool p) {
    int sz = p ? 4 : 0;
    asm volatile("cp.async.ca.shared.global [%0], [%1], 4, %2;"
                 :: "r"(dst), "l"(src), "r"(sz));
}
#define CP_COMMIT() asm volatile("cp.async.commit_group;" ::: "memory")
#define CP_WAIT(n)  asm volatile("cp.async.wait_group %0;" :: "n"(n) : "memory")

__device__ __forceinline__ void ldsm4(uint32_t& r0, uint32_t& r1,
                                      uint32_t& r2, uint32_t& r3, uint32_t addr) {
    asm volatile("ldmatrix.sync.aligned.m8n8.x4.shared.b16 {%0,%1,%2,%3}, [%4];"
                 : "=r"(r0), "=r"(r1), "=r"(r2), "=r"(r3) : "r"(addr));
}
__device__ __forceinline__ void mma16816(float* c, const uint32_t* a,
                                         uint32_t b0, uint32_t b1) {
    asm volatile(
        "mma.sync.aligned.m16n8k16.row.col.f32.bf16.bf16.f32 "
        "{%0,%1,%2,%3}, {%4,%5,%6,%7}, {%8,%9}, {%0,%1,%2,%3};"
        : "+f"(c[0]), "+f"(c[1]), "+f"(c[2]), "+f"(c[3])
        : "r"(a[0]), "r"(a[1]), "r"(a[2]), "r"(a[3]), "r"(b0), "r"(b1));
}
__device__ __forceinline__ void mma1688_tf32(float* c, const uint32_t* a,
                                             uint32_t b0, uint32_t b1) {
    asm volatile(
        "mma.sync.aligned.m16n8k8.row.col.f32.tf32.tf32.f32 "
        "{%0,%1,%2,%3}, {%4,%5,%6,%7}, {%8,%9}, {%0,%1,%2,%3};"
        : "+f"(c[0]), "+f"(c[1]), "+f"(c[2]), "+f"(c[3])
        : "r"(a[0]), "r"(a[1]), "r"(a[2]), "r"(a[3]), "r"(b0), "r"(b1));
}
__device__ __forceinline__ float tf32r(float x) {
    uint32_t u;
    asm("cvt.rna.tf32.f32 %0, %1;" : "=r"(u) : "f"(x));
    return __uint_as_float(u);
}

// ---------------------------------------------------------------------------
// Flash attention: O[c][q] = sum_j softmax_j(Q[q]·K[j]/16) V[c][j]
// Q tile 64 q-rows, KV tiles 64, online softmax, all intermediates on-chip.
// 8 warps: 4m x 2n.  S warp tile 16x32; O warp tile 16x128.
// grid (HW/64, BATCH), 256 threads.
// ---------------------------------------------------------------------------
#define FA_QPITCH 528          // bytes: 264 bf16 (stride mod 128B = 4 words)
#define FA_VPITCH 144          // bytes: 72 bf16
#define FA_Q 0
#define FA_KSZ (64 * FA_QPITCH)            // 33792
#define FA_K0 FA_KSZ
#define FA_VSZ (256 * FA_VPITCH)           // 36864
#define FA_V0 (FA_K0 + 2 * FA_KSZ)         // 101376
#define FA_P  (FA_V0 + 2 * FA_VSZ)         // 175104 (64 x 144)
#define FA_RMX (FA_P + 64 * FA_VPITCH)     // 184320: float[2][64]
#define FA_RSM (FA_RMX + 512)
#define FA_SMEM (FA_RSM + 512)             // 185344

__device__ __forceinline__ void fa_stage_kv(
    uint32_t sb, const __nv_bfloat16* __restrict__ kT,
    const __nv_bfloat16* __restrict__ vbf, int kv0, int buf, int tid)
{
    const uint32_t kd = sb + FA_K0 + buf * FA_KSZ;
    const uint32_t vd = sb + FA_V0 + buf * FA_VSZ;
    #pragma unroll
    for (int i = 0; i < 8; i++) {
        const int ch = tid + i * 256;
        const int r = ch >> 5, s = ch & 31;
        cp16(kd + r * FA_QPITCH + s * 16, kT + (size_t)(kv0 + r) * CDIM + s * 8);
    }
    #pragma unroll
    for (int i = 0; i < 8; i++) {
        const int ch = tid + i * 256;
        const int r = ch >> 3, s = ch & 7;
        cp16(vd + r * FA_VPITCH + s * 16, vbf + (size_t)r * HW + kv0 + s * 8);
    }
}

__global__ __launch_bounds__(256, 1) void flash_attn_kernel(
    const __nv_bfloat16* __restrict__ qT, const __nv_bfloat16* __restrict__ kT,
    const __nv_bfloat16* __restrict__ vbf, float* __restrict__ O)
{
    extern __shared__ char smem[];
    const uint32_t sb = smem_u32(smem);
    const int tid = threadIdx.x, lane = tid & 31, wid = tid >> 5;
    const int wm = wid & 3, wn = wid >> 2;
    const int z = blockIdx.y;
    const int bm = blockIdx.x * 64;
    qT  += (size_t)z * HW * CDIM + (size_t)bm * CDIM;
    kT  += (size_t)z * HW * CDIM;
    vbf += (size_t)z * CDIM * HW;
    O   += (size_t)z * CDIM * HW;

    // load Q tile [64][256]
    #pragma unroll
    for (int i = 0; i < 8; i++) {
        const int ch = tid + i * 256;
        const int r = ch >> 5, s = ch & 31;
        cp16(sb + FA_Q + r * FA_QPITCH + s * 16, qT + (size_t)r * CDIM + s * 8);
    }
    CP_COMMIT();
    fa_stage_kv(sb, kT, vbf, 0, 0, tid);
    CP_COMMIT();

    float o[16][4];
    #pragma unroll
    for (int nt = 0; nt < 16; nt++)
        o[nt][0] = o[nt][1] = o[nt][2] = o[nt][3] = 0.f;
    float m0 = -1e30f, m1 = -1e30f, l0 = 0.f, l1 = 0.f;

    const int r_lo = lane >> 2;
    const int row0 = wm * 16 + r_lo;
    const int a_r  = lane & 15;
    const int a_kc = (lane >> 4) << 3;
    const int b_r  = (lane & 7) + ((lane >> 4) << 3);
    const int b_kc = ((lane >> 3) & 1) << 3;
    float* redmx = (float*)(smem + FA_RMX);
    float* redsm = (float*)(smem + FA_RSM);

    const int NI = HW / 64;
    for (int it = 0; it < NI; it++) {
        if (it + 1 < NI) {
            fa_stage_kv(sb, kT, vbf, (it + 1) * 64, (it + 1) & 1, tid);
            CP_COMMIT();
            CP_WAIT(1);
        } else {
            CP_WAIT(0);
        }
        __syncthreads();

        const uint32_t kb = sb + FA_K0 + (it & 1) * FA_KSZ;
        const uint32_t vb = sb + FA_V0 + (it & 1) * FA_VSZ;

        // ---- S = (Q K^T) / 16 : warp tile 16 x 32 ----
        float s_[4][4];
        #pragma unroll
        for (int nt = 0; nt < 4; nt++)
            s_[nt][0] = s_[nt][1] = s_[nt][2] = s_[nt][3] = 0.f;
        #pragma unroll
        for (int ks = 0; ks < 16; ks++) {
            const int kk = ks * 16;
            uint32_t a[4];
            ldsm4(a[0], a[1], a[2], a[3],
                  sb + FA_Q + (wm * 16 + a_r) * FA_QPITCH + (kk + a_kc) * 2);
            uint32_t b[4][2];
            #pragma unroll
            for (int p = 0; p < 2; p++) {
                const int nr = wn * 32 + p * 16 + b_r;
                ldsm4(b[2 * p][0], b[2 * p][1], b[2 * p + 1][0], b[2 * p + 1][1],
                      kb + nr * FA_QPITCH + (kk + b_kc) * 2);
            }
            #pragma unroll
            for (int nt = 0; nt < 4; nt++) mma16816(s_[nt], a, b[nt][0], b[nt][1]);
        }
        #pragma unroll
        for (int nt = 0; nt < 4; nt++) {
            s_[nt][0] *= 0.0625f; s_[nt][1] *= 0.0625f;
            s_[nt][2] *= 0.0625f; s_[nt][3] *= 0.0625f;
        }

        // ---- tile row max (intra-warp then cross-warp) ----
        float mx0 = -1e30f, mx1 = -1e30f;
        #pragma unroll
        for (int nt = 0; nt < 4; nt++) {
            mx0 = fmaxf(mx0, fmaxf(s_[nt][0], s_[nt][1]));
            mx1 = fmaxf(mx1, fmaxf(s_[nt][2], s_[nt][3]));
        }
        mx0 = fmaxf(mx0, __shfl_xor_sync(0xffffffff, mx0, 1));
        mx0 = fmaxf(mx0, __shfl_xor_sync(0xffffffff, mx0, 2));
        mx1 = fmaxf(mx1, __shfl_xor_sync(0xffffffff, mx1, 1));
        mx1 = fmaxf(mx1, __shfl_xor_sync(0xffffffff, mx1, 2));
        if ((lane & 3) == 0) {
            redmx[wn * 64 + row0]     = mx0;
            redmx[wn * 64 + row0 + 8] = mx1;
        }
        __syncthreads();
        const float tm0 = fmaxf(redmx[row0], redmx[64 + row0]);
        const float tm1 = fmaxf(redmx[row0 + 8], redmx[64 + row0 + 8]);
        const float mn0 = fmaxf(m0, tm0), mn1 = fmaxf(m1, tm1);
        const float al0 = __expf(m0 - mn0), al1 = __expf(m1 - mn1);
        m0 = mn0; m1 = mn1;

        // ---- P = exp(S - m), partial row sums, P -> smem bf16 ----
        float sum0 = 0.f, sum1 = 0.f;
        #pragma unroll
        for (int nt = 0; nt < 4; nt++) {
            const float p0 = __expf(s_[nt][0] - m0), p1 = __expf(s_[nt][1] - m0);
            const float p2 = __expf(s_[nt][2] - m1), p3 = __expf(s_[nt][3] - m1);
            sum0 += p0 + p1; sum1 += p2 + p3;
            const int col = wn * 32 + nt * 8 + (lane & 3) * 2;
            __nv_bfloat162 lo = __floats2bfloat162_rn(p0, p1);
            __nv_bfloat162 hi = __floats2bfloat162_rn(p2, p3);
            asm volatile("st.shared.b32 [%0], %1;"
                :: "r"(sb + FA_P + row0 * FA_VPITCH + col * 2),
                   "r"(*(uint32_t*)&lo) : "memory");
            asm volatile("st.shared.b32 [%0], %1;"
                :: "r"(sb + FA_P + (row0 + 8) * FA_VPITCH + col * 2),
                   "r"(*(uint32_t*)&hi) : "memory");
        }
        sum0 += __shfl_xor_sync(0xffffffff, sum0, 1);
        sum0 += __shfl_xor_sync(0xffffffff, sum0, 2);
        sum1 += __shfl_xor_sync(0xffffffff, sum1, 1);
        sum1 += __shfl_xor_sync(0xffffffff, sum1, 2);
        if ((lane & 3) == 0) {
            redsm[wn * 64 + row0]     = sum0;
            redsm[wn * 64 + row0 + 8] = sum1;
        }
        __syncthreads();
        l0 = l0 * al0 + redsm[row0] + redsm[64 + row0];
        l1 = l1 * al1 + redsm[row0 + 8] + redsm[64 + row0 + 8];

        // ---- rescale O, then O += P V^T : warp tile 16 x 128 ----
        #pragma unroll
        for (int nt = 0; nt < 16; nt++) {
            o[nt][0] *= al0; o[nt][1] *= al0;
            o[nt][2] *= al1; o[nt][3] *= al1;
        }
        #pragma unroll
        for (int ks = 0; ks < 4; ks++) {
            const int kk = ks * 16;
            uint32_t a[4];
            ldsm4(a[0], a[1], a[2], a[3],
                  sb + FA_P + (wm * 16 + a_r) * FA_VPITCH + (kk + a_kc) * 2);
            #pragma unroll
            for (int p = 0; p < 8; p++) {
                uint32_t b0, b1, b2, b3;
                const int nr = wn * 128 + p * 16 + b_r;
                ldsm4(b0, b1, b2, b3, vb + nr * FA_VPITCH + (kk + b_kc) * 2);
                mma16816(o[2 * p], a, b0, b1);
                mma16816(o[2 * p + 1], a, b2, b3);
            }
        }
        __syncthreads();
    }

    // ---- epilogue: O /= l, tf32-round, store as [C][HW] ----
    const float i0 = 1.f / l0, i1 = 1.f / l1;
    const int q0 = bm + row0;
    #pragma unroll
    for (int nt = 0; nt < 16; nt++) {
        const int c = wn * 128 + nt * 8 + (lane & 3) * 2;
        O[(size_t)c * HW + q0]           = tf32r(o[nt][0] * i0);
        O[(size_t)(c + 1) * HW + q0]     = tf32r(o[nt][1] * i0);
        O[(size_t)c * HW + q0 + 8]       = tf32r(o[nt][2] * i1);
        O[(size_t)(c + 1) * HW + q0 + 8] = tf32r(o[nt][3] * i1);
    }
}

// ---------------------------------------------------------------------------
// TF32 GEMM (convs / qkv / out) — unchanged from R5
// ---------------------------------------------------------------------------
#define TF_APITCH 36
#define TF_BPITCH 132
#define TF_ASTG (128 * TF_APITCH * 4)
#define TF_BSTG (32 * TF_BPITCH * 4)
#define TF_STAGE (TF_ASTG + TF_BSTG)
#define TF_SMEM (2 * TF_STAGE)

__device__ __forceinline__ void tf_stage_a(
    uint32_t sbA, const float* __restrict__ A, int K, int k0, int tid)
{
    #pragma unroll
    for (int i = 0; i < 4; i++) {
        const int v = tid + i * 256;
        const int r = v >> 3, sub = v & 7;
        cp16(sbA + (r * TF_APITCH + sub * 4) * 4, A + (size_t)r * K + k0 + sub * 4);
    }
}
__device__ __forceinline__ void tf_stage_kn(
    uint32_t sbB, const float* __restrict__ B, int k0, int bn, int tid)
{
    #pragma unroll
    for (int i = 0; i < 4; i++) {
        const int v = tid + i * 256;
        const int k = v >> 5, sub = v & 31;
        cp16(sbB + (k * TF_BPITCH + sub * 4) * 4,
             B + (size_t)(k0 + k) * 4096 + bn + sub * 4);
    }
}
__device__ __forceinline__ void tf_stage_conv(
    uint32_t sbB, const float* __restrict__ B, int k0, int bn, int tid)
{
    const int n = tid & 127, th = tid >> 7;
    const int nn = bn + n;
    const int y0 = nn >> 6, x0 = nn & 63;
    #pragma unroll
    for (int i = 0; i < 16; i++) {
        const int k = 2 * i + th;
        const int kk = k0 + k;
        const int ci = kk / 9;
        const int tap = kk - ci * 9;
        const int t3 = tap / 3;
        const int dy = t3 - 1, dx = tap - t3 * 3 - 1;
        const int y = y0 + dy, x = x0 + dx;
        const bool p = ((unsigned)x < 64u) && ((unsigned)y < 64u);
        cp4_pred(sbB + (k * TF_BPITCH + n) * 4, B + ci * 4096 + y * 64 + x, p);
    }
}

template<int BMODE>
__global__ __launch_bounds__(256, 2) void tf32_gemm_kernel(
    const float* __restrict__ A, const float* __restrict__ B, float* __restrict__ C,
    int M, int K, long sB, long sC,
    const float* __restrict__ bias, const float* __restrict__ bias2,
    const float* __restrict__ res)
{
    extern __shared__ char smem[];
    const uint32_t sb = smem_u32(smem);
    const int tid = threadIdx.x;
    const int wid = tid >> 5, lane = tid & 31;
    const int wm = wid & 3, wn = wid >> 2;
    const int z = blockIdx.z;
    const int bm = blockIdx.y * 128, bn = blockIdx.x * 128;
    A += (size_t)bm * K;
    B += (size_t)z * sB;
    C += (size_t)z * sC;
    const float* rp = res ? res + (size_t)z * sC : nullptr;

    float acc[2][8][4];
    #pragma unroll
    for (int mt = 0; mt < 2; mt++)
        #pragma unroll
        for (int nt = 0; nt < 8; nt++)
            #pragma unroll
            for (int e = 0; e < 4; e++) acc[mt][nt][e] = 0.f;

    const int S = K >> 5;
    tf_stage_a(sb, A, K, 0, tid);
    if (BMODE == 0) tf_stage_kn(sb + TF_ASTG, B, 0, bn, tid);
    else            tf_stage_conv(sb + TF_ASTG, B, 0, bn, tid);
    CP_COMMIT();

    for (int s = 0; s < S; s++) {
        if (s + 1 < S) {
            const uint32_t nb = sb + ((s + 1) & 1) * TF_STAGE;
            tf_stage_a(nb, A, K, (s + 1) << 5, tid);
            if (BMODE == 0) tf_stage_kn(nb + TF_ASTG, B, (s + 1) << 5, bn, tid);
            else            tf_stage_conv(nb + TF_ASTG, B, (s + 1) << 5, bn, tid);
            CP_COMMIT();
            CP_WAIT(1);
        } else {
            CP_WAIT(0);
        }
        __syncthreads();

        const float* cA = (const float*)(smem + (s & 1) * TF_STAGE);
        const float* cB = (const float*)(smem + (s & 1) * TF_STAGE + TF_ASTG);
        #pragma unroll
        for (int ks = 0; ks < 4; ks++) {
            const int kk = ks * 8;
            uint32_t a[2][4];
            #pragma unroll
            for (int mt = 0; mt < 2; mt++) {
                const int m = wm * 32 + mt * 16 + (lane >> 2);
                const float* p = cA + m * TF_APITCH + kk + (lane & 3);
                a[mt][0] = __float_as_uint(p[0]);
                a[mt][1] = __float_as_uint(p[8 * TF_APITCH]);
                a[mt][2] = __float_as_uint(p[4]);
                a[mt][3] = __float_as_uint(p[8 * TF_APITCH + 4]);
            }
            #pragma unroll
            for (int nt = 0; nt < 8; nt++) {
                const int n = wn * 64 + nt * 8 + (lane >> 2);
                const float* p = cB + (kk + (lane & 3)) * TF_BPITCH + n;
                const uint32_t b0 = __float_as_uint(p[0]);
                const uint32_t b1 = __float_as_uint(p[4 * TF_BPITCH]);
                mma1688_tf32(acc[0][nt], a[0], b0, b1);
                mma1688_tf32(acc[1][nt], a[1], b0, b1);
            }
        }
        __syncthreads();
    }

    #pragma unroll
    for (int mt = 0; mt < 2; mt++) {
        const int r0 = bm + wm * 32 + mt * 16 + (lane >> 2);
        float bb0 = 0.f, bb1 = 0.f;
        if (bias)  { bb0 = bias[r0]; bb1 = bias[r0 + 8]; }
        if (bias2) { bb0 += bias2[z * M + r0]; bb1 += bias2[z * M + r0 + 8]; }
        #pragma unroll
        for (int nt = 0; nt < 8; nt++) {
            const int col = bn + wn * 64 + nt * 8 + (lane & 3) * 2;
            const size_t o0 = (size_t)r0 * 4096 + col;
            const size_t o1 = o0 + (size_t)8 * 4096;
            float2 v0 = { acc[mt][nt][0] + bb0, acc[mt][nt][1] + bb0 };
            float2 v1 = { acc[mt][nt][2] + bb1, acc[mt][nt][3] + bb1 };
            if (rp) {
                float2 q0 = *(const float2*)(rp + o0);
                float2 q1 = *(const float2*)(rp + o1);
                v0.x += q0.x; v0.y += q0.y; v1.x += q1.x; v1.y += q1.y;
            }
            *(float2*)(C + o0) = v0;
            *(float2*)(C + o1) = v1;
        }
    }
}

__global__ __launch_bounds__(256) void tf32_round_kernel(
    const float* __restrict__ in, float* __restrict__ out, int n4)
{
    const int i = blockIdx.x * 256 + threadIdx.x;
    if (i < n4) {
        float4 v = ((const float4*)in)[i];
        v.x = tf32r(v.x); v.y = tf32r(v.y); v.z = tf32r(v.z); v.w = tf32r(v.w);
        ((float4*)out)[i] = v;
    }
}

// ---------------------------------------------------------------------------
// Transpose+convert: q,k fp32 [C][HW] -> bf16 [HW][C]
// ---------------------------------------------------------------------------
__global__ __launch_bounds__(256) void transpose_cvt_kernel(
    const float* __restrict__ qkv, __nv_bfloat16* __restrict__ qT,
    __nv_bfloat16* __restrict__ kT)
{
    __shared__ float tile[32][33];
    const int b = blockIdx.z >> 1, which = blockIdx.z & 1;
    const float* s = qkv + (size_t)b * (3 * CDIM * HW)
                   + (size_t)(which * CDIM + blockIdx.y * 32) * HW + blockIdx.x * 32;
    __nv_bfloat16* d = (which ? kT : qT) + (size_t)b * HW * CDIM
                     + (size_t)(blockIdx.x * 32) * CDIM + blockIdx.y * 32;
    const int tx = threadIdx.x & 31, ty = threadIdx.x >> 5;
    #pragma unroll
    for (int r = 0; r < 32; r += 8)
        tile[ty + r][tx] = s[(size_t)(ty + r) * HW + tx];
    __syncthreads();
    #pragma unroll
    for (int r = 0; r < 32; r += 8)
        d[(size_t)(ty + r) * CDIM + tx] = __float2bfloat16(tile[tx][ty + r]);
}

__global__ __launch_bounds__(256) void cvt_v_kernel(
    const float* __restrict__ qkv, __nv_bfloat16* __restrict__ v)
{
    const size_t i = (size_t)blockIdx.x * 1024 + threadIdx.x * 4;
    const size_t z = blockIdx.y;
    float4 f = *(const float4*)(qkv + z * (size_t)(3 * CDIM * HW)
                                + (size_t)2 * CDIM * HW + i);
    __nv_bfloat162 lo = __floats2bfloat162_rn(f.x, f.y);
    __nv_bfloat162 hi = __floats2bfloat162_rn(f.z, f.w);
    uint2 o = { *(uint32_t*)&lo, *(uint32_t*)&hi };
    *(uint2*)(v + z * (size_t)(CDIM * HW) + i) = o;
}

// ---------------------------------------------------------------------------
// GroupNorm (+ optional SiLU, + optional tf32 rounding)
// ---------------------------------------------------------------------------
__global__ __launch_bounds__(256) void groupnorm_kernel(
    const float* __restrict__ in, float* __restrict__ out,
    const float* __restrict__ sc, const float* __restrict__ bi,
    int do_silu, int do_round)
{
    __shared__ float s_sum[256], s_sq[256];
    __shared__ float s_stats[2];
    const int t = threadIdx.x;
    const int bg = blockIdx.x;
    const size_t base = (size_t)bg * 32768;
    const int g = bg & 31;

    float sum = 0.f, sq = 0.f;
    for (int i = t * 4; i < 32768; i += 1024) {
        float4 v = *(const float4*)&in[base + i];
        sum += v.x + v.y + v.z + v.w;
        sq  += v.x*v.x + v.y*v.y + v.z*v.z + v.w*v.w;
    }
    s_sum[t] = sum; s_sq[t] = sq;
    __syncthreads();
    for (int s = 128; s > 0; s >>= 1) {
        if (t < s) { s_sum[t] += s_sum[t + s]; s_sq[t] += s_sq[t + s]; }
        __syncthreads();
    }
    if (t == 0) {
        float mean = s_sum[0] * (1.f / 32768.f);
        float var  = s_sq[0] * (1.f / 32768.f) - mean * mean;
        s_stats[0] = mean;
        s_stats[1] = rsqrtf(var + 1e-5f);
    }
    __syncthreads();
    const float mean = s_stats[0], rstd = s_stats[1];

    for (int i = t * 4; i < 32768; i += 1024) {
        const int c = (g << 3) + (i >> 12);
        const float a = sc[c] * rstd;
        const float b2 = bi[c] - mean * a;
        float4 v = *(const float4*)&in[base + i];
        float4 o;
        o.x = v.x * a + b2; o.y = v.y * a + b2;
        o.z = v.z * a + b2; o.w = v.w * a + b2;
        if (do_silu) {
            o.x = o.x / (1.f + __expf(-o.x));
            o.y = o.y / (1.f + __expf(-o.y));
            o.z = o.z / (1.f + __expf(-o.z));
            o.w = o.w / (1.f + __expf(-o.w));
        }
        if (do_round) {
            o.x = tf32r(o.x); o.y = tf32r(o.y);
            o.z = tf32r(o.z); o.w = tf32r(o.w);
        }
        *(float4*)&out[base + i] = o;
    }
}

// ---------------------------------------------------------------------------
// time-MLP
// ---------------------------------------------------------------------------
__global__ __launch_bounds__(256) void mlp_kernel(
    const float* __restrict__ te, const float* __restrict__ w,
    const float* __restrict__ mb, float* __restrict__ temb)
{
    __shared__ float s[TDIM];
    const int b = blockIdx.x, t = threadIdx.x;
    for (int i = t; i < TDIM; i += 256) {
        float v = te[b * TDIM + i];
        s[i] = v / (1.f + __expf(-v));
    }
    __syncthreads();
    float acc = 0.f;
    for (int k = 0; k < TDIM; k++) acc = fmaf(s[k], w[k * CDIM + t], acc);
    temb[b * CDIM + t] = acc + mb[t];
}

// ---------------------------------------------------------------------------
// Launch
// ---------------------------------------------------------------------------
extern "C" void kernel_launch(void* const* d_in, const int* in_sizes, int n_in,
                              void* d_out, int out_size)
{
    const float* x        = (const float*)d_in[0];
    const float* time_emb = (const float*)d_in[1];
    const float* gn1_s    = (const float*)d_in[2];
    const float* gn1_b    = (const float*)d_in[3];
    const float* conv1_w  = (const float*)d_in[4];
    const float* conv1_b  = (const float*)d_in[5];
    const float* mlp_w    = (const float*)d_in[6];
    const float* mlp_b    = (const float*)d_in[7];
    const float* gn2_s    = (const float*)d_in[8];
    const float* gn2_b    = (const float*)d_in[9];
    const float* conv2_w  = (const float*)d_in[10];
    const float* conv2_b  = (const float*)d_in[11];
    const float* an_s     = (const float*)d_in[12];
    const float* an_b     = (const float*)d_in[13];
    const float* qkv_w    = (const float*)d_in[14];
    const float* qkv_b    = (const float*)d_in[15];
    const float* out_w    = (const float*)d_in[16];
    const float* out_b    = (const float*)d_in[17];
    float* out = (float*)d_out;

    float *bufA, *bufB, *qkvb, *temb, *w1r, *w2r, *wqr, *wor;
    __nv_bfloat16 *qT, *kT, *vbf;
    cudaGetSymbolAddress((void**)&bufA, g_bufA);
    cudaGetSymbolAddress((void**)&bufB, g_bufB);
    cudaGetSymbolAddress((void**)&qkvb, g_qkv);
    cudaGetSymbolAddress((void**)&temb, g_temb);
    cudaGetSymbolAddress((void**)&w1r,  g_w1r);
    cudaGetSymbolAddress((void**)&w2r,  g_w2r);
    cudaGetSymbolAddress((void**)&wqr,  g_wqr);
    cudaGetSymbolAddress((void**)&wor,  g_wor);
    cudaGetSymbolAddress((void**)&qT,   g_qT);
    cudaGetSymbolAddress((void**)&kT,   g_kT);
    cudaGetSymbolAddress((void**)&vbf,  g_vbf);

    cudaFuncSetAttribute(tf32_gemm_kernel<0>,
                         cudaFuncAttributeMaxDynamicSharedMemorySize, TF_SMEM);
    cudaFuncSetAttribute(tf32_gemm_kernel<1>,
                         cudaFuncAttributeMaxDynamicSharedMemorySize, TF_SMEM);
    cudaFuncSetAttribute(flash_attn_kernel,
                         cudaFuncAttributeMaxDynamicSharedMemorySize, FA_SMEM);

    const long sAct = (long)CDIM * HW;
    const long sQkv = (long)3 * CDIM * HW;

    tf32_round_kernel<<<576, 256>>>(conv1_w, w1r, CDIM * CDIM * 9 / 4);
    tf32_round_kernel<<<576, 256>>>(conv2_w, w2r, CDIM * CDIM * 9 / 4);
    tf32_round_kernel<<<192, 256>>>(qkv_w, wqr, 3 * CDIM * CDIM / 4);
    tf32_round_kernel<<<64, 256>>>(out_w, wor, CDIM * CDIM / 4);

    mlp_kernel<<<BATCH, 256>>>(time_emb, mlp_w, mlp_b, temb);

    groupnorm_kernel<<<BATCH * 32, 256>>>(x, bufA, gn1_s, gn1_b, 1, 1);
    tf32_gemm_kernel<1><<<dim3(32, 2, BATCH), 256, TF_SMEM>>>(
        w1r, bufA, bufB, CDIM, CDIM * 9, sAct, sAct, conv1_b, temb, nullptr);
    groupnorm_kernel<<<BATCH * 32, 256>>>(bufB, bufA, gn2_s, gn2_b, 1, 1);
    tf32_gemm_kernel<1><<<dim3(32, 2, BATCH), 256, TF_SMEM>>>(
        w2r, bufA, bufB, CDIM, CDIM * 9, sAct, sAct, conv2_b, nullptr, x);
    groupnorm_kernel<<<BATCH * 32, 256>>>(bufB, bufA, an_s, an_b, 0, 1);
    tf32_gemm_kernel<0><<<dim3(32, 6, BATCH), 256, TF_SMEM>>>(
        wqr, bufA, qkvb, 3 * CDIM, CDIM, sAct, sQkv, qkv_b, nullptr, nullptr);

    transpose_cvt_kernel<<<dim3(HW / 32, CDIM / 32, BATCH * 2), 256>>>(qkvb, qT, kT);
    cvt_v_kernel<<<dim3(1024, BATCH), 256>>>(qkvb, vbf);

    // fused attention: O (tf32-rounded, [C][HW]) -> bufA
    flash_attn_kernel<<<dim3(HW / 64, BATCH), 256, FA_SMEM>>>(qT, kT, vbf, bufA);

    // out = W_out @ O + out_b + xr
    tf32_gemm_kernel<0><<<dim3(32, 2, BATCH), 256, TF_SMEM>>>(
        wor, bufA, out, CDIM, CDIM, sAct, sAct, out_b, nullptr, bufB);
}

// round 7
// speedup vs baseline: 1.1447x; 1.1447x over previous
#include <cuda_runtime.h>
#include <cuda_bf16.h>
#include <cstdint>
#include <cstddef>

#define BATCH 8
#define CDIM 256
#define HW 4096
#define TDIM 1024

// ---------------------------------------------------------------------------
// Static scratch (allocation forbidden)
// ---------------------------------------------------------------------------
__device__ float g_bufA[(size_t)BATCH * CDIM * HW];
__device__ float g_bufB[(size_t)BATCH * CDIM * HW];
__device__ float g_qkv [(size_t)BATCH * 3 * CDIM * HW];
__device__ float g_temb[BATCH * CDIM];
__device__ __nv_bfloat16 g_qT [(size_t)BATCH * HW * CDIM];
__device__ __nv_bfloat16 g_kT [(size_t)BATCH * HW * CDIM];
__device__ __nv_bfloat16 g_vbf[(size_t)BATCH * CDIM * HW];
__device__ float g_w1r[CDIM * CDIM * 9];
__device__ float g_w2r[CDIM * CDIM * 9];
__device__ float g_wqr[3 * CDIM * CDIM];
__device__ float g_wor[CDIM * CDIM];

// ---------------------------------------------------------------------------
// PTX helpers
// ---------------------------------------------------------------------------
__device__ __forceinline__ uint32_t smem_u32(const void* p) {
    uint32_t a;
    asm("{ .reg .u64 t; cvta.to.shared.u64 t, %1; cvt.u32.u64 %0, t; }"
        : "=r"(a) : "l"(p));
    return a;
}
__device__ __forceinline__ void cp16(uint32_t dst, const void* src) {
    asm volatile("cp.async.cg.shared.global [%0], [%1], 16;" :: "r"(dst), "l"(src));
}
__device__ __forceinline__ void cp4_pred(uint32_t dst, const void* src, bool p) {
    int sz = p ? 4 : 0;
    asm volatile("cp.async.ca.shared.global [%0], [%1], 4, %2;"
                 :: "r"(dst), "l"(src), "r"(sz));
}
#define CP_COMMIT() asm volatile("cp.async.commit_group;" ::: "memory")
#define CP_WAIT(n)  asm volatile("cp.async.wait_group %0;" :: "n"(n) : "memory")

__device__ __forceinline__ void ldsm4(uint32_t& r0, uint32_t& r1,
                                      uint32_t& r2, uint32_t& r3, uint32_t addr) {
    asm volatile("ldmatrix.sync.aligned.m8n8.x4.shared.b16 {%0,%1,%2,%3}, [%4];"
                 : "=r"(r0), "=r"(r1), "=r"(r2), "=r"(r3) : "r"(addr));
}
__device__ __forceinline__ void mma16816(float* c, const uint32_t* a,
                                         uint32_t b0, uint32_t b1) {
    asm volatile(
        "mma.sync.aligned.m16n8k16.row.col.f32.bf16.bf16.f32 "
        "{%0,%1,%2,%3}, {%4,%5,%6,%7}, {%8,%9}, {%0,%1,%2,%3};"
        : "+f"(c[0]), "+f"(c[1]), "+f"(c[2]), "+f"(c[3])
        : "r"(a[0]), "r"(a[1]), "r"(a[2]), "r"(a[3]), "r"(b0), "r"(b1));
}
__device__ __forceinline__ void mma1688_tf32(float* c, const uint32_t* a,
                                             uint32_t b0, uint32_t b1) {
    asm volatile(
        "mma.sync.aligned.m16n8k8.row.col.f32.tf32.tf32.f32 "
        "{%0,%1,%2,%3}, {%4,%5,%6,%7}, {%8,%9}, {%0,%1,%2,%3};"
        : "+f"(c[0]), "+f"(c[1]), "+f"(c[2]), "+f"(c[3])
        : "r"(a[0]), "r"(a[1]), "r"(a[2]), "r"(a[3]), "r"(b0), "r"(b1));
}
__device__ __forceinline__ float tf32r(float x) {
    uint32_t u;
    asm("cvt.rna.tf32.f32 %0, %1;" : "=r"(u) : "f"(x));
    return __uint_as_float(u);
}

// ---------------------------------------------------------------------------
// FA2 flash attention: O[c][q] = sum_j softmax_j(Q[q]·K[j]/16) V[c][j]
// Q tile 128 rows; 8 warps, warp w owns rows [16w,16w+16), FULL 64-wide KV
// tile per warp. P stays in registers (S-accum == A-fragment layout).
// One __syncthreads per KV iteration. grid (HW/128, BATCH), 256 threads.
// ---------------------------------------------------------------------------
#define FB_QPITCH 528                      // 264 bf16; 132 words % 32 = 4
#define FB_VPITCH 144                      // 72 bf16; 36 words % 32 = 4
#define FB_QSZ (128 * FB_QPITCH)           // 67584
#define FB_K0 FB_QSZ
#define FB_KSZ (64 * FB_QPITCH)            // 33792
#define FB_V0 (FB_K0 + 2 * FB_KSZ)         // 135168
#define FB_VSZ (256 * FB_VPITCH)           // 36864
#define FB_SMEM (FB_V0 + 2 * FB_VSZ)       // 208896
#define FB_OPITCH 132                      // fp32 words, % 4 == 0 for float4

__device__ __forceinline__ void fb_stage_kv(
    uint32_t sb, const __nv_bfloat16* __restrict__ kT,
    const __nv_bfloat16* __restrict__ vbf, int kv0, int buf, int tid)
{
    const uint32_t kd = sb + FB_K0 + buf * FB_KSZ;
    const uint32_t vd = sb + FB_V0 + buf * FB_VSZ;
    #pragma unroll
    for (int i = 0; i < 8; i++) {
        const int ch = tid + i * 256;
        const int r = ch >> 5, s = ch & 31;
        cp16(kd + r * FB_QPITCH + s * 16, kT + (size_t)(kv0 + r) * CDIM + s * 8);
    }
    #pragma unroll
    for (int i = 0; i < 8; i++) {
        const int ch = tid + i * 256;
        const int r = ch >> 3, s = ch & 7;
        cp16(vd + r * FB_VPITCH + s * 16, vbf + (size_t)r * HW + kv0 + s * 8);
    }
}

__global__ __launch_bounds__(256, 1) void flash2_kernel(
    const __nv_bfloat16* __restrict__ qT, const __nv_bfloat16* __restrict__ kT,
    const __nv_bfloat16* __restrict__ vbf, float* __restrict__ O)
{
    extern __shared__ char smem[];
    const uint32_t sb = smem_u32(smem);
    const int tid = threadIdx.x, lane = tid & 31, wid = tid >> 5;
    const int z = blockIdx.y;
    const int bm = blockIdx.x * 128;
    qT  += (size_t)z * HW * CDIM + (size_t)bm * CDIM;
    kT  += (size_t)z * HW * CDIM;
    vbf += (size_t)z * CDIM * HW;
    O   += (size_t)z * CDIM * HW;

    // Q tile [128][256] bf16
    #pragma unroll
    for (int i = 0; i < 16; i++) {
        const int ch = tid + i * 256;
        const int r = ch >> 5, s = ch & 31;
        cp16(sb + r * FB_QPITCH + s * 16, qT + (size_t)r * CDIM + s * 8);
    }
    CP_COMMIT();
    fb_stage_kv(sb, kT, vbf, 0, 0, tid);
    CP_COMMIT();

    float o[32][4];
    #pragma unroll
    for (int nt = 0; nt < 32; nt++)
        o[nt][0] = o[nt][1] = o[nt][2] = o[nt][3] = 0.f;
    float m0 = -1e30f, m1 = -1e30f, l0 = 0.f, l1 = 0.f;

    const int r_lo = lane >> 2;
    const int qrow = wid * 16;
    const int a_r  = lane & 15;
    const int a_kc = (lane >> 4) << 3;
    const int b_r  = (lane & 7) + ((lane >> 4) << 3);
    const int b_kc = ((lane >> 3) & 1) << 3;

    const int NI = HW / 64;
    for (int it = 0; it < NI; it++) {
        if (it + 1 < NI) {
            fb_stage_kv(sb, kT, vbf, (it + 1) * 64, (it + 1) & 1, tid);
            CP_COMMIT();
            CP_WAIT(1);
        } else {
            CP_WAIT(0);
        }
        __syncthreads();

        const uint32_t kb = sb + FB_K0 + (it & 1) * FB_KSZ;
        const uint32_t vb = sb + FB_V0 + (it & 1) * FB_VSZ;

        // ---- S = (Q K^T)/16 : warp tile 16 x 64 ----
        float s_[8][4];
        #pragma unroll
        for (int nt = 0; nt < 8; nt++)
            s_[nt][0] = s_[nt][1] = s_[nt][2] = s_[nt][3] = 0.f;
        #pragma unroll
        for (int ks = 0; ks < 16; ks++) {
            const int kk = ks * 16;
            uint32_t a[4];
            ldsm4(a[0], a[1], a[2], a[3],
                  sb + (qrow + a_r) * FB_QPITCH + (kk + a_kc) * 2);
            #pragma unroll
            for (int p = 0; p < 4; p++) {
                uint32_t b0, b1, b2, b3;
                ldsm4(b0, b1, b2, b3, kb + (p * 16 + b_r) * FB_QPITCH + (kk + b_kc) * 2);
                mma16816(s_[2 * p], a, b0, b1);
                mma16816(s_[2 * p + 1], a, b2, b3);
            }
        }

        // ---- row max (pure shfl; rows owned by this warp) ----
        float mx0 = -1e30f, mx1 = -1e30f;
        #pragma unroll
        for (int nt = 0; nt < 8; nt++) {
            mx0 = fmaxf(mx0, fmaxf(s_[nt][0], s_[nt][1]));
            mx1 = fmaxf(mx1, fmaxf(s_[nt][2], s_[nt][3]));
        }
        mx0 = fmaxf(mx0, __shfl_xor_sync(0xffffffff, mx0, 1));
        mx0 = fmaxf(mx0, __shfl_xor_sync(0xffffffff, mx0, 2));
        mx1 = fmaxf(mx1, __shfl_xor_sync(0xffffffff, mx1, 1));
        mx1 = fmaxf(mx1, __shfl_xor_sync(0xffffffff, mx1, 2));
        mx0 *= 0.0625f; mx1 *= 0.0625f;
        const float mn0 = fmaxf(m0, mx0), mn1 = fmaxf(m1, mx1);
        const float al0 = __expf(m0 - mn0), al1 = __expf(m1 - mn1);
        m0 = mn0; m1 = mn1;

        // ---- P = exp(S/16 - m) -> registers (A-fragment layout) ----
        uint32_t p_[8][2];
        float sum0 = 0.f, sum1 = 0.f;
        #pragma unroll
        for (int nt = 0; nt < 8; nt++) {
            const float p0 = __expf(fmaf(s_[nt][0], 0.0625f, -m0));
            const float p1 = __expf(fmaf(s_[nt][1], 0.0625f, -m0));
            const float p2 = __expf(fmaf(s_[nt][2], 0.0625f, -m1));
            const float p3 = __expf(fmaf(s_[nt][3], 0.0625f, -m1));
            sum0 += p0 + p1; sum1 += p2 + p3;
            __nv_bfloat162 lo = __floats2bfloat162_rn(p0, p1);
            __nv_bfloat162 hi = __floats2bfloat162_rn(p2, p3);
            p_[nt][0] = *(uint32_t*)&lo;
            p_[nt][1] = *(uint32_t*)&hi;
        }
        sum0 += __shfl_xor_sync(0xffffffff, sum0, 1);
        sum0 += __shfl_xor_sync(0xffffffff, sum0, 2);
        sum1 += __shfl_xor_sync(0xffffffff, sum1, 1);
        sum1 += __shfl_xor_sync(0xffffffff, sum1, 2);
        l0 = l0 * al0 + sum0;
        l1 = l1 * al1 + sum1;

        // ---- O = O*alpha + P V^T : warp tile 16 x 256 ----
        #pragma unroll
        for (int nt = 0; nt < 32; nt++) {
            o[nt][0] *= al0; o[nt][1] *= al0;
            o[nt][2] *= al1; o[nt][3] *= al1;
        }
        #pragma unroll
        for (int kbs = 0; kbs < 4; kbs++) {
            uint32_t a[4] = { p_[2 * kbs][0], p_[2 * kbs][1],
                              p_[2 * kbs + 1][0], p_[2 * kbs + 1][1] };
            #pragma unroll
            for (int p = 0; p < 16; p++) {
                uint32_t b0, b1, b2, b3;
                ldsm4(b0, b1, b2, b3,
                      vb + (p * 16 + b_r) * FB_VPITCH + (kbs * 16 + b_kc) * 2);
                mma16816(o[2 * p], a, b0, b1);
                mma16816(o[2 * p + 1], a, b2, b3);
            }
        }
        __syncthreads();
    }

    // ---- epilogue: O/l, tf32 round, stage [C][q] in smem, coalesced store ----
    const float i0 = 1.f / l0, i1 = 1.f / l1;
    float* os = (float*)(smem + FB_K0);
    #pragma unroll
    for (int nt = 0; nt < 32; nt++) {
        const int c = nt * 8 + (lane & 3) * 2;
        const int q = qrow + r_lo;
        os[c * FB_OPITCH + q]           = tf32r(o[nt][0] * i0);
        os[(c + 1) * FB_OPITCH + q]     = tf32r(o[nt][1] * i0);
        os[c * FB_OPITCH + q + 8]       = tf32r(o[nt][2] * i1);
        os[(c + 1) * FB_OPITCH + q + 8] = tf32r(o[nt][3] * i1);
    }
    __syncthreads();
    #pragma unroll
    for (int i = 0; i < 32; i++) {
        const int f = tid + i * 256;
        const int r = f >> 5, cq = (f & 31) * 4;
        float4 v = *(float4*)(os + r * FB_OPITCH + cq);
        *(float4*)(O + (size_t)r * HW + bm + cq) = v;
    }
}

// ---------------------------------------------------------------------------
// TF32 GEMM (convs / qkv / out) — unchanged
// ---------------------------------------------------------------------------
#define TF_APITCH 36
#define TF_BPITCH 132
#define TF_ASTG (128 * TF_APITCH * 4)
#define TF_BSTG (32 * TF_BPITCH * 4)
#define TF_STAGE (TF_ASTG + TF_BSTG)
#define TF_SMEM (2 * TF_STAGE)

__device__ __forceinline__ void tf_stage_a(
    uint32_t sbA, const float* __restrict__ A, int K, int k0, int tid)
{
    #pragma unroll
    for (int i = 0; i < 4; i++) {
        const int v = tid + i * 256;
        const int r = v >> 3, sub = v & 7;
        cp16(sbA + (r * TF_APITCH + sub * 4) * 4, A + (size_t)r * K + k0 + sub * 4);
    }
}
__device__ __forceinline__ void tf_stage_kn(
    uint32_t sbB, const float* __restrict__ B, int k0, int bn, int tid)
{
    #pragma unroll
    for (int i = 0; i < 4; i++) {
        const int v = tid + i * 256;
        const int k = v >> 5, sub = v & 31;
        cp16(sbB + (k * TF_BPITCH + sub * 4) * 4,
             B + (size_t)(k0 + k) * 4096 + bn + sub * 4);
    }
}
__device__ __forceinline__ void tf_stage_conv(
    uint32_t sbB, const float* __restrict__ B, int k0, int bn, int tid)
{
    const int n = tid & 127, th = tid >> 7;
    const int nn = bn + n;
    const int y0 = nn >> 6, x0 = nn & 63;
    #pragma unroll
    for (int i = 0; i < 16; i++) {
        const int k = 2 * i + th;
        const int kk = k0 + k;
        const int ci = kk / 9;
        const int tap = kk - ci * 9;
        const int t3 = tap / 3;
        const int dy = t3 - 1, dx = tap - t3 * 3 - 1;
        const int y = y0 + dy, x = x0 + dx;
        const bool p = ((unsigned)x < 64u) && ((unsigned)y < 64u);
        cp4_pred(sbB + (k * TF_BPITCH + n) * 4, B + ci * 4096 + y * 64 + x, p);
    }
}

template<int BMODE>
__global__ __launch_bounds__(256, 2) void tf32_gemm_kernel(
    const float* __restrict__ A, const float* __restrict__ B, float* __restrict__ C,
    int M, int K, long sB, long sC,
    const float* __restrict__ bias, const float* __restrict__ bias2,
    const float* __restrict__ res)
{
    extern __shared__ char smem[];
    const uint32_t sb = smem_u32(smem);
    const int tid = threadIdx.x;
    const int wid = tid >> 5, lane = tid & 31;
    const int wm = wid & 3, wn = wid >> 2;
    const int z = blockIdx.z;
    const int bm = blockIdx.y * 128, bn = blockIdx.x * 128;
    A += (size_t)bm * K;
    B += (size_t)z * sB;
    C += (size_t)z * sC;
    const float* rp = res ? res + (size_t)z * sC : nullptr;

    float acc[2][8][4];
    #pragma unroll
    for (int mt = 0; mt < 2; mt++)
        #pragma unroll
        for (int nt = 0; nt < 8; nt++)
            #pragma unroll
            for (int e = 0; e < 4; e++) acc[mt][nt][e] = 0.f;

    const int S = K >> 5;
    tf_stage_a(sb, A, K, 0, tid);
    if (BMODE == 0) tf_stage_kn(sb + TF_ASTG, B, 0, bn, tid);
    else            tf_stage_conv(sb + TF_ASTG, B, 0, bn, tid);
    CP_COMMIT();

    for (int s = 0; s < S; s++) {
        if (s + 1 < S) {
            const uint32_t nb = sb + ((s + 1) & 1) * TF_STAGE;
            tf_stage_a(nb, A, K, (s + 1) << 5, tid);
            if (BMODE == 0) tf_stage_kn(nb + TF_ASTG, B, (s + 1) << 5, bn, tid);
            else            tf_stage_conv(nb + TF_ASTG, B, (s + 1) << 5, bn, tid);
            CP_COMMIT();
            CP_WAIT(1);
        } else {
            CP_WAIT(0);
        }
        __syncthreads();

        const float* cA = (const float*)(smem + (s & 1) * TF_STAGE);
        const float* cB = (const float*)(smem + (s & 1) * TF_STAGE + TF_ASTG);
        #pragma unroll
        for (int ks = 0; ks < 4; ks++) {
            const int kk = ks * 8;
            uint32_t a[2][4];
            #pragma unroll
            for (int mt = 0; mt < 2; mt++) {
                const int m = wm * 32 + mt * 16 + (lane >> 2);
                const float* p = cA + m * TF_APITCH + kk + (lane & 3);
                a[mt][0] = __float_as_uint(p[0]);
                a[mt][1] = __float_as_uint(p[8 * TF_APITCH]);
                a[mt][2] = __float_as_uint(p[4]);
                a[mt][3] = __float_as_uint(p[8 * TF_APITCH + 4]);
            }
            #pragma unroll
            for (int nt = 0; nt < 8; nt++) {
                const int n = wn * 64 + nt * 8 + (lane >> 2);
                const float* p = cB + (kk + (lane & 3)) * TF_BPITCH + n;
                const uint32_t b0 = __float_as_uint(p[0]);
                const uint32_t b1 = __float_as_uint(p[4 * TF_BPITCH]);
                mma1688_tf32(acc[0][nt], a[0], b0, b1);
                mma1688_tf32(acc[1][nt], a[1], b0, b1);
            }
        }
        __syncthreads();
    }

    #pragma unroll
    for (int mt = 0; mt < 2; mt++) {
        const int r0 = bm + wm * 32 + mt * 16 + (lane >> 2);
        float bb0 = 0.f, bb1 = 0.f;
        if (bias)  { bb0 = bias[r0]; bb1 = bias[r0 + 8]; }
        if (bias2) { bb0 += bias2[z * M + r0]; bb1 += bias2[z * M + r0 + 8]; }
        #pragma unroll
        for (int nt = 0; nt < 8; nt++) {
            const int col = bn + wn * 64 + nt * 8 + (lane & 3) * 2;
            const size_t o0 = (size_t)r0 * 4096 + col;
            const size_t o1 = o0 + (size_t)8 * 4096;
            float2 v0 = { acc[mt][nt][0] + bb0, acc[mt][nt][1] + bb0 };
            float2 v1 = { acc[mt][nt][2] + bb1, acc[mt][nt][3] + bb1 };
            if (rp) {
                float2 q0 = *(const float2*)(rp + o0);
                float2 q1 = *(const float2*)(rp + o1);
                v0.x += q0.x; v0.y += q0.y; v1.x += q1.x; v1.y += q1.y;
            }
            *(float2*)(C + o0) = v0;
            *(float2*)(C + o1) = v1;
        }
    }
}

__global__ __launch_bounds__(256) void tf32_round_kernel(
    const float* __restrict__ in, float* __restrict__ out, int n4)
{
    const int i = blockIdx.x * 256 + threadIdx.x;
    if (i < n4) {
        float4 v = ((const float4*)in)[i];
        v.x = tf32r(v.x); v.y = tf32r(v.y); v.z = tf32r(v.z); v.w = tf32r(v.w);
        ((float4*)out)[i] = v;
    }
}

// ---------------------------------------------------------------------------
// Transpose+convert: q,k fp32 [C][HW] -> bf16 [HW][C]
// ---------------------------------------------------------------------------
__global__ __launch_bounds__(256) void transpose_cvt_kernel(
    const float* __restrict__ qkv, __nv_bfloat16* __restrict__ qT,
    __nv_bfloat16* __restrict__ kT)
{
    __shared__ float tile[32][33];
    const int b = blockIdx.z >> 1, which = blockIdx.z & 1;
    const float* s = qkv + (size_t)b * (3 * CDIM * HW)
                   + (size_t)(which * CDIM + blockIdx.y * 32) * HW + blockIdx.x * 32;
    __nv_bfloat16* d = (which ? kT : qT) + (size_t)b * HW * CDIM
                     + (size_t)(blockIdx.x * 32) * CDIM + blockIdx.y * 32;
    const int tx = threadIdx.x & 31, ty = threadIdx.x >> 5;
    #pragma unroll
    for (int r = 0; r < 32; r += 8)
        tile[ty + r][tx] = s[(size_t)(ty + r) * HW + tx];
    __syncthreads();
    #pragma unroll
    for (int r = 0; r < 32; r += 8)
        d[(size_t)(ty + r) * CDIM + tx] = __float2bfloat16(tile[tx][ty + r]);
}

__global__ __launch_bounds__(256) void cvt_v_kernel(
    const float* __restrict__ qkv, __nv_bfloat16* __restrict__ v)
{
    const size_t i = (size_t)blockIdx.x * 1024 + threadIdx.x * 4;
    const size_t z = blockIdx.y;
    float4 f = *(const float4*)(qkv + z * (size_t)(3 * CDIM * HW)
                                + (size_t)2 * CDIM * HW + i);
    __nv_bfloat162 lo = __floats2bfloat162_rn(f.x, f.y);
    __nv_bfloat162 hi = __floats2bfloat162_rn(f.z, f.w);
    uint2 o = { *(uint32_t*)&lo, *(uint32_t*)&hi };
    *(uint2*)(v + z * (size_t)(CDIM * HW) + i) = o;
}

// ---------------------------------------------------------------------------
// GroupNorm (+ optional SiLU, + optional tf32 rounding)
// ---------------------------------------------------------------------------
__global__ __launch_bounds__(256) void groupnorm_kernel(
    const float* __restrict__ in, float* __restrict__ out,
    const float* __restrict__ sc, const float* __restrict__ bi,
    int do_silu, int do_round)
{
    __shared__ float s_sum[256], s_sq[256];
    __shared__ float s_stats[2];
    const int t = threadIdx.x;
    const int bg = blockIdx.x;
    const size_t base = (size_t)bg * 32768;
    const int g = bg & 31;

    float sum = 0.f, sq = 0.f;
    for (int i = t * 4; i < 32768; i += 1024) {
        float4 v = *(const float4*)&in[base + i];
        sum += v.x + v.y + v.z + v.w;
        sq  += v.x*v.x + v.y*v.y + v.z*v.z + v.w*v.w;
    }
    s_sum[t] = sum; s_sq[t] = sq;
    __syncthreads();
    for (int s = 128; s > 0; s >>= 1) {
        if (t < s) { s_sum[t] += s_sum[t + s]; s_sq[t] += s_sq[t + s]; }
        __syncthreads();
    }
    if (t == 0) {
        float mean = s_sum[0] * (1.f / 32768.f);
        float var  = s_sq[0] * (1.f / 32768.f) - mean * mean;
        s_stats[0] = mean;
        s_stats[1] = rsqrtf(var + 1e-5f);
    }
    __syncthreads();
    const float mean = s_stats[0], rstd = s_stats[1];

    for (int i = t * 4; i < 32768; i += 1024) {
        const int c = (g << 3) + (i >> 12);
        const float a = sc[c] * rstd;
        const float b2 = bi[c] - mean * a;
        float4 v = *(const float4*)&in[base + i];
        float4 o;
        o.x = v.x * a + b2; o.y = v.y * a + b2;
        o.z = v.z * a + b2; o.w = v.w * a + b2;
        if (do_silu) {
            o.x = o.x / (1.f + __expf(-o.x));
            o.y = o.y / (1.f + __expf(-o.y));
            o.z = o.z / (1.f + __expf(-o.z));
            o.w = o.w / (1.f + __expf(-o.w));
        }
        if (do_round) {
            o.x = tf32r(o.x); o.y = tf32r(o.y);
            o.z = tf32r(o.z); o.w = tf32r(o.w);
        }
        *(float4*)&out[base + i] = o;
    }
}

// ---------------------------------------------------------------------------
// time-MLP
// ---------------------------------------------------------------------------
__global__ __launch_bounds__(256) void mlp_kernel(
    const float* __restrict__ te, const float* __restrict__ w,
    const float* __restrict__ mb, float* __restrict__ temb)
{
    __shared__ float s[TDIM];
    const int b = blockIdx.x, t = threadIdx.x;
    for (int i = t; i < TDIM; i += 256) {
        float v = te[b * TDIM + i];
        s[i] = v / (1.f + __expf(-v));
    }
    __syncthreads();
    float acc = 0.f;
    for (int k = 0; k < TDIM; k++) acc = fmaf(s[k], w[k * CDIM + t], acc);
    temb[b * CDIM + t] = acc + mb[t];
}

// ---------------------------------------------------------------------------
// Launch
// ---------------------------------------------------------------------------
extern "C" void kernel_launch(void* const* d_in, const int* in_sizes, int n_in,
                              void* d_out, int out_size)
{
    const float* x        = (const float*)d_in[0];
    const float* time_emb = (const float*)d_in[1];
    const float* gn1_s    = (const float*)d_in[2];
    const float* gn1_b    = (const float*)d_in[3];
    const float* conv1_w  = (const float*)d_in[4];
    const float* conv1_b  = (const float*)d_in[5];
    const float* mlp_w    = (const float*)d_in[6];
    const float* mlp_b    = (const float*)d_in[7];
    const float* gn2_s    = (const float*)d_in[8];
    const float* gn2_b    = (const float*)d_in[9];
    const float* conv2_w  = (const float*)d_in[10];
    const float* conv2_b  = (const float*)d_in[11];
    const float* an_s     = (const float*)d_in[12];
    const float* an_b     = (const float*)d_in[13];
    const float* qkv_w    = (const float*)d_in[14];
    const float* qkv_b    = (const float*)d_in[15];
    const float* out_w    = (const float*)d_in[16];
    const float* out_b    = (const float*)d_in[17];
    float* out = (float*)d_out;

    float *bufA, *bufB, *qkvb, *temb, *w1r, *w2r, *wqr, *wor;
    __nv_bfloat16 *qT, *kT, *vbf;
    cudaGetSymbolAddress((void**)&bufA, g_bufA);
    cudaGetSymbolAddress((void**)&bufB, g_bufB);
    cudaGetSymbolAddress((void**)&qkvb, g_qkv);
    cudaGetSymbolAddress((void**)&temb, g_temb);
    cudaGetSymbolAddress((void**)&w1r,  g_w1r);
    cudaGetSymbolAddress((void**)&w2r,  g_w2r);
    cudaGetSymbolAddress((void**)&wqr,  g_wqr);
    cudaGetSymbolAddress((void**)&wor,  g_wor);
    cudaGetSymbolAddress((void**)&qT,   g_qT);
    cudaGetSymbolAddress((void**)&kT,   g_kT);
    cudaGetSymbolAddress((void**)&vbf,  g_vbf);

    cudaFuncSetAttribute(tf32_gemm_kernel<0>,
                         cudaFuncAttributeMaxDynamicSharedMemorySize, TF_SMEM);
    cudaFuncSetAttribute(tf32_gemm_kernel<1>,
                         cudaFuncAttributeMaxDynamicSharedMemorySize, TF_SMEM);
    cudaFuncSetAttribute(flash2_kernel,
                         cudaFuncAttributeMaxDynamicSharedMemorySize, FB_SMEM);

    const long sAct = (long)CDIM * HW;
    const long sQkv = (long)3 * CDIM * HW;

    tf32_round_kernel<<<576, 256>>>(conv1_w, w1r, CDIM * CDIM * 9 / 4);
    tf32_round_kernel<<<576, 256>>>(conv2_w, w2r, CDIM * CDIM * 9 / 4);
    tf32_round_kernel<<<192, 256>>>(qkv_w, wqr, 3 * CDIM * CDIM / 4);
    tf32_round_kernel<<<64, 256>>>(out_w, wor, CDIM * CDIM / 4);

    mlp_kernel<<<BATCH, 256>>>(time_emb, mlp_w, mlp_b, temb);

    groupnorm_kernel<<<BATCH * 32, 256>>>(x, bufA, gn1_s, gn1_b, 1, 1);
    tf32_gemm_kernel<1><<<dim3(32, 2, BATCH), 256, TF_SMEM>>>(
        w1r, bufA, bufB, CDIM, CDIM * 9, sAct, sAct, conv1_b, temb, nullptr);
    groupnorm_kernel<<<BATCH * 32, 256>>>(bufB, bufA, gn2_s, gn2_b, 1, 1);
    tf32_gemm_kernel<1><<<dim3(32, 2, BATCH), 256, TF_SMEM>>>(
        w2r, bufA, bufB, CDIM, CDIM * 9, sAct, sAct, conv2_b, nullptr, x);
    groupnorm_kernel<<<BATCH * 32, 256>>>(bufB, bufA, an_s, an_b, 0, 1);
    tf32_gemm_kernel<0><<<dim3(32, 6, BATCH), 256, TF_SMEM>>>(
        wqr, bufA, qkvb, 3 * CDIM, CDIM, sAct, sQkv, qkv_b, nullptr, nullptr);

    transpose_cvt_kernel<<<dim3(HW / 32, CDIM / 32, BATCH * 2), 256>>>(qkvb, qT, kT);
    cvt_v_kernel<<<dim3(1024, BATCH), 256>>>(qkvb, vbf);

    // FA2 fused attention: O (tf32-rounded, [C][HW]) -> bufA
    flash2_kernel<<<dim3(HW / 128, BATCH), 256, FB_SMEM>>>(qT, kT, vbf, bufA);

    // out = W_out @ O + out_b + xr
    tf32_gemm_kernel<0><<<dim3(32, 2, BATCH), 256, TF_SMEM>>>(
        wor, bufA, out, CDIM, CDIM, sAct, sAct, out_b, nullptr, bufB);
}

// round 8
// speedup vs baseline: 1.4387x; 1.2568x over previous
#include <cuda_runtime.h>
#include <cuda_bf16.h>
#include <cstdint>
#include <cstddef>

#define BATCH 8
#define CDIM 256
#define HW 4096
#define TDIM 1024

// ---------------------------------------------------------------------------
// Static scratch (allocation forbidden)
// ---------------------------------------------------------------------------
__device__ float g_bufA[(size_t)BATCH * CDIM * HW];
__device__ float g_bufB[(size_t)BATCH * CDIM * HW];
__device__ float g_temb[BATCH * CDIM];
__device__ __nv_bfloat16 g_qT [(size_t)BATCH * HW * CDIM];
__device__ __nv_bfloat16 g_kT [(size_t)BATCH * HW * CDIM];
__device__ __nv_bfloat16 g_vbf[(size_t)BATCH * CDIM * HW];
__device__ float g_w1p[CDIM * CDIM * 9];     // permuted [m][chunk][tap][ci32]
__device__ float g_w2p[CDIM * CDIM * 9];
__device__ float g_wqr[3 * CDIM * CDIM];
__device__ float g_wor[CDIM * CDIM];

// ---------------------------------------------------------------------------
// PTX helpers
// ---------------------------------------------------------------------------
__device__ __forceinline__ uint32_t smem_u32(const void* p) {
    uint32_t a;
    asm("{ .reg .u64 t; cvta.to.shared.u64 t, %1; cvt.u32.u64 %0, t; }"
        : "=r"(a) : "l"(p));
    return a;
}
__device__ __forceinline__ void cp16(uint32_t dst, const void* src) {
    asm volatile("cp.async.cg.shared.global [%0], [%1], 16;" :: "r"(dst), "l"(src));
}
__device__ __forceinline__ void cp16_pred(uint32_t dst, const void* src, bool p) {
    int sz = p ? 16 : 0;
    asm volatile("cp.async.cg.shared.global [%0], [%1], 16, %2;"
                 :: "r"(dst), "l"(src), "r"(sz));
}
#define CP_COMMIT() asm volatile("cp.async.commit_group;" ::: "memory")
#define CP_WAIT(n)  asm volatile("cp.async.wait_group %0;" :: "n"(n) : "memory")

__device__ __forceinline__ void ldsm4(uint32_t& r0, uint32_t& r1,
                                      uint32_t& r2, uint32_t& r3, uint32_t addr) {
    asm volatile("ldmatrix.sync.aligned.m8n8.x4.shared.b16 {%0,%1,%2,%3}, [%4];"
                 : "=r"(r0), "=r"(r1), "=r"(r2), "=r"(r3) : "r"(addr));
}
__device__ __forceinline__ void mma16816(float* c, const uint32_t* a,
                                         uint32_t b0, uint32_t b1) {
    asm volatile(
        "mma.sync.aligned.m16n8k16.row.col.f32.bf16.bf16.f32 "
        "{%0,%1,%2,%3}, {%4,%5,%6,%7}, {%8,%9}, {%0,%1,%2,%3};"
        : "+f"(c[0]), "+f"(c[1]), "+f"(c[2]), "+f"(c[3])
        : "r"(a[0]), "r"(a[1]), "r"(a[2]), "r"(a[3]), "r"(b0), "r"(b1));
}
__device__ __forceinline__ void mma1688_tf32(float* c, const uint32_t* a,
                                             uint32_t b0, uint32_t b1) {
    asm volatile(
        "mma.sync.aligned.m16n8k8.row.col.f32.tf32.tf32.f32 "
        "{%0,%1,%2,%3}, {%4,%5,%6,%7}, {%8,%9}, {%0,%1,%2,%3};"
        : "+f"(c[0]), "+f"(c[1]), "+f"(c[2]), "+f"(c[3])
        : "r"(a[0]), "r"(a[1]), "r"(a[2]), "r"(a[3]), "r"(b0), "r"(b1));
}
__device__ __forceinline__ float tf32r(float x) {
    uint32_t u;
    asm("cvt.rna.tf32.f32 %0, %1;" : "=r"(u) : "f"(x));
    return __uint_as_float(u);
}

// ---------------------------------------------------------------------------
// TF32 3x3 conv kernel (raw-tile loader, 9 shifted-view taps).
// C[m][n] = sum_{ci,tap} Wp[m][c][tap][ci] * X[ci][y(n)+dy][x(n)+dx]
// Wp: permuted weights [256m][8 chunk][9 tap][32 ci].
// X:  [256 ci][64][64] fp32 (tf32-rounded), batch stride sB.
// Tile 128m x 128n (= 2 image rows). 8 warps (4m x 2n). BK per tap = 32 ci.
// Smem: raw B tile [32ci][4 rows][72 pitch] x2 buf + A slab [128][36] x2.
// grid (32, 2, BATCH), 256 threads.
// ---------------------------------------------------------------------------
#define CV_ROWW 72
#define CV_CIW 296                            // 4*72 + 8 (bank skew)
#define CV_BRAW (32 * CV_CIW * 4)             // 37888 B per buffer
#define CV_ABUF (128 * 36 * 4)                // 18432 B per buffer
#define CV_SMEM (2 * CV_BRAW + 2 * CV_ABUF)   // 112640

__device__ __forceinline__ void cv_stage_b_slice(
    uint32_t sb, const float* __restrict__ X, int chunk, int buf,
    int slice, int Y0, int tid)
{
    const int f = slice * 256 + tid;          // 0..2047
    const int ci = f >> 6, rr = f & 63;
    const int yy = rr >> 4, s2 = rr & 15;
    const int y = Y0 - 1 + yy;
    const bool valid = (unsigned)y < 64u;
    const uint32_t dst = sb + buf * CV_BRAW + (ci * CV_CIW + yy * CV_ROWW + 4 + s2 * 4) * 4;
    cp16_pred(dst, X + (size_t)(chunk * 32 + ci) * 4096 + y * 64 + s2 * 4, valid);
}
__device__ __forceinline__ void cv_stage_a(
    uint32_t sb, const float* __restrict__ Wp, int chunk, int tap, int buf, int tid)
{
    #pragma unroll
    for (int i = 0; i < 4; i++) {
        const int f = tid + i * 256;
        const int m = f >> 3, s = f & 7;
        cp16(sb + 2 * CV_BRAW + buf * CV_ABUF + (m * 36 + s * 4) * 4,
             Wp + (size_t)m * 2304 + chunk * 288 + tap * 32 + s * 4);
    }
}

__global__ __launch_bounds__(256, 2) void tf32_conv_kernel(
    const float* __restrict__ Wp, const float* __restrict__ X, float* __restrict__ C,
    long sB, long sC,
    const float* __restrict__ bias, const float* __restrict__ bias2,
    const float* __restrict__ res)
{
    extern __shared__ char smem[];
    const uint32_t sb = smem_u32(smem);
    const int tid = threadIdx.x;
    const int wid = tid >> 5, lane = tid & 31;
    const int wm = wid & 3, wn = wid >> 2;
    const int r4 = lane & 3, q4 = lane >> 2;
    const int z = blockIdx.z;
    const int bm = blockIdx.y * 128, bn = blockIdx.x * 128;
    const int Y0 = bn >> 6;
    Wp += (size_t)bm * 2304;
    X += (size_t)z * sB;
    C += (size_t)z * sC;
    const float* rp = res ? res + (size_t)z * sC : nullptr;

    // zero halo columns (x=3, x=68) of both raw buffers
    #pragma unroll
    for (int j = 0; j < 2; j++) {
        const int idx = tid + j * 256;
        const int b = idx >> 8, r = idx & 255;
        const int ci = r >> 3, yy = (r >> 1) & 3, side = r & 1;
        ((float*)smem)[b * (CV_BRAW / 4) + ci * CV_CIW + yy * CV_ROWW + (side ? 68 : 3)] = 0.f;
    }

    // prologue: full B(chunk 0) + A(0,0)
    #pragma unroll
    for (int s = 0; s < 8; s++) cv_stage_b_slice(sb, X, 0, 0, s, Y0, tid);
    cv_stage_a(sb, Wp, 0, 0, 0, tid);
    CP_COMMIT();

    float acc[2][8][4];
    #pragma unroll
    for (int mt = 0; mt < 2; mt++)
        #pragma unroll
        for (int nt = 0; nt < 8; nt++)
            #pragma unroll
            for (int e = 0; e < 4; e++) acc[mt][nt][e] = 0.f;

    int iter = 0;
    for (int c = 0; c < 8; c++) {
        #pragma unroll
        for (int t = 0; t < 9; t++) {
            CP_WAIT(0);
            __syncthreads();
            // prefetch next A slab + one slice of next chunk's raw B
            if (!(c == 7 && t == 8)) {
                const int c2 = (t == 8) ? c + 1 : c;
                const int t2 = (t == 8) ? 0 : t + 1;
                cv_stage_a(sb, Wp, c2, t2, (iter + 1) & 1, tid);
                if (c < 7 && t < 8) cv_stage_b_slice(sb, X, c + 1, (c + 1) & 1, t, Y0, tid);
                CP_COMMIT();
            }
            // compute tap t of chunk c
            const int dy = t / 3 - 1, dx = t - (t / 3) * 3 - 1;
            const float* aB = (const float*)(smem + 2 * CV_BRAW + (iter & 1) * CV_ABUF);
            const float* bB = (const float*)(smem + (c & 1) * CV_BRAW);
            const int bofs = (wn + dy + 1) * CV_ROWW + dx + 4 + q4;
            #pragma unroll
            for (int ks = 0; ks < 4; ks++) {
                const int kk = ks * 8;
                uint32_t a[2][4];
                #pragma unroll
                for (int mt = 0; mt < 2; mt++) {
                    const int m = wm * 32 + mt * 16 + q4;
                    const float* p = aB + m * 36 + kk + r4;
                    a[mt][0] = __float_as_uint(p[0]);
                    a[mt][1] = __float_as_uint(p[8 * 36]);
                    a[mt][2] = __float_as_uint(p[4]);
                    a[mt][3] = __float_as_uint(p[8 * 36 + 4]);
                }
                const int cib = (kk + r4) * CV_CIW;
                #pragma unroll
                for (int nt = 0; nt < 8; nt++) {
                    const uint32_t b0 = __float_as_uint(bB[cib + bofs + nt * 8]);
                    const uint32_t b1 = __float_as_uint(bB[cib + 4 * CV_CIW + bofs + nt * 8]);
                    mma1688_tf32(acc[0][nt], a[0], b0, b1);
                    mma1688_tf32(acc[1][nt], a[1], b0, b1);
                }
            }
            iter++;
        }
    }

    // epilogue
    #pragma unroll
    for (int mt = 0; mt < 2; mt++) {
        const int r0 = bm + wm * 32 + mt * 16 + q4;
        float bb0 = 0.f, bb1 = 0.f;
        if (bias)  { bb0 = bias[r0]; bb1 = bias[r0 + 8]; }
        if (bias2) { bb0 += bias2[z * 256 + r0]; bb1 += bias2[z * 256 + r0 + 8]; }
        #pragma unroll
        for (int nt = 0; nt < 8; nt++) {
            const int col = bn + wn * 64 + nt * 8 + r4 * 2;
            const size_t o0 = (size_t)r0 * 4096 + col;
            const size_t o1 = o0 + (size_t)8 * 4096;
            float2 v0 = { acc[mt][nt][0] + bb0, acc[mt][nt][1] + bb0 };
            float2 v1 = { acc[mt][nt][2] + bb1, acc[mt][nt][3] + bb1 };
            if (rp) {
                float2 u0 = *(const float2*)(rp + o0);
                float2 u1 = *(const float2*)(rp + o1);
                v0.x += u0.x; v0.y += u0.y; v1.x += u1.x; v1.y += u1.y;
            }
            *(float2*)(C + o0) = v0;
            *(float2*)(C + o1) = v1;
        }
    }
}

// ---------------------------------------------------------------------------
// TF32 GEMM (out projection): C = A*B + bias + res
// ---------------------------------------------------------------------------
#define TF_APITCH 36
#define TF_BPITCH 132
#define TF_ASTG (128 * TF_APITCH * 4)
#define TF_BSTG (32 * TF_BPITCH * 4)
#define TF_STAGE (TF_ASTG + TF_BSTG)
#define TF_SMEM (2 * TF_STAGE)

__device__ __forceinline__ void tf_stage_a(
    uint32_t sbA, const float* __restrict__ A, int K, int k0, int tid)
{
    #pragma unroll
    for (int i = 0; i < 4; i++) {
        const int v = tid + i * 256;
        const int r = v >> 3, sub = v & 7;
        cp16(sbA + (r * TF_APITCH + sub * 4) * 4, A + (size_t)r * K + k0 + sub * 4);
    }
}
__device__ __forceinline__ void tf_stage_kn(
    uint32_t sbB, const float* __restrict__ B, int k0, int bn, int tid)
{
    #pragma unroll
    for (int i = 0; i < 4; i++) {
        const int v = tid + i * 256;
        const int k = v >> 5, sub = v & 31;
        cp16(sbB + (k * TF_BPITCH + sub * 4) * 4,
             B + (size_t)(k0 + k) * 4096 + bn + sub * 4);
    }
}

// shared mainloop body macro-free: plain function for out-GEMM
__global__ __launch_bounds__(256, 2) void tf32_gemm_kernel(
    const float* __restrict__ A, const float* __restrict__ B, float* __restrict__ C,
    int M, int K, long sB, long sC,
    const float* __restrict__ bias, const float* __restrict__ res)
{
    extern __shared__ char smem[];
    const uint32_t sb = smem_u32(smem);
    const int tid = threadIdx.x;
    const int wid = tid >> 5, lane = tid & 31;
    const int wm = wid & 3, wn = wid >> 2;
    const int z = blockIdx.z;
    const int bm = blockIdx.y * 128, bn = blockIdx.x * 128;
    A += (size_t)bm * K;
    B += (size_t)z * sB;
    C += (size_t)z * sC;
    const float* rp = res ? res + (size_t)z * sC : nullptr;

    float acc[2][8][4];
    #pragma unroll
    for (int mt = 0; mt < 2; mt++)
        #pragma unroll
        for (int nt = 0; nt < 8; nt++)
            #pragma unroll
            for (int e = 0; e < 4; e++) acc[mt][nt][e] = 0.f;

    const int S = K >> 5;
    tf_stage_a(sb, A, K, 0, tid);
    tf_stage_kn(sb + TF_ASTG, B, 0, bn, tid);
    CP_COMMIT();

    for (int s = 0; s < S; s++) {
        if (s + 1 < S) {
            const uint32_t nb = sb + ((s + 1) & 1) * TF_STAGE;
            tf_stage_a(nb, A, K, (s + 1) << 5, tid);
            tf_stage_kn(nb + TF_ASTG, B, (s + 1) << 5, bn, tid);
            CP_COMMIT();
            CP_WAIT(1);
        } else {
            CP_WAIT(0);
        }
        __syncthreads();

        const float* cA = (const float*)(smem + (s & 1) * TF_STAGE);
        const float* cB = (const float*)(smem + (s & 1) * TF_STAGE + TF_ASTG);
        #pragma unroll
        for (int ks = 0; ks < 4; ks++) {
            const int kk = ks * 8;
            uint32_t a[2][4];
            #pragma unroll
            for (int mt = 0; mt < 2; mt++) {
                const int m = wm * 32 + mt * 16 + (lane >> 2);
                const float* p = cA + m * TF_APITCH + kk + (lane & 3);
                a[mt][0] = __float_as_uint(p[0]);
                a[mt][1] = __float_as_uint(p[8 * TF_APITCH]);
                a[mt][2] = __float_as_uint(p[4]);
                a[mt][3] = __float_as_uint(p[8 * TF_APITCH + 4]);
            }
            #pragma unroll
            for (int nt = 0; nt < 8; nt++) {
                const int n = wn * 64 + nt * 8 + (lane >> 2);
                const float* p = cB + (kk + (lane & 3)) * TF_BPITCH + n;
                const uint32_t b0 = __float_as_uint(p[0]);
                const uint32_t b1 = __float_as_uint(p[4 * TF_BPITCH]);
                mma1688_tf32(acc[0][nt], a[0], b0, b1);
                mma1688_tf32(acc[1][nt], a[1], b0, b1);
            }
        }
        __syncthreads();
    }

    #pragma unroll
    for (int mt = 0; mt < 2; mt++) {
        const int r0 = bm + wm * 32 + mt * 16 + (lane >> 2);
        float bb0 = 0.f, bb1 = 0.f;
        if (bias) { bb0 = bias[r0]; bb1 = bias[r0 + 8]; }
        #pragma unroll
        for (int nt = 0; nt < 8; nt++) {
            const int col = bn + wn * 64 + nt * 8 + (lane & 3) * 2;
            const size_t o0 = (size_t)r0 * 4096 + col;
            const size_t o1 = o0 + (size_t)8 * 4096;
            float2 v0 = { acc[mt][nt][0] + bb0, acc[mt][nt][1] + bb0 };
            float2 v1 = { acc[mt][nt][2] + bb1, acc[mt][nt][3] + bb1 };
            if (rp) {
                float2 q0 = *(const float2*)(rp + o0);
                float2 q1 = *(const float2*)(rp + o1);
                v0.x += q0.x; v0.y += q0.y; v1.x += q1.x; v1.y += q1.y;
            }
            *(float2*)(C + o0) = v0;
            *(float2*)(C + o1) = v1;
        }
    }
}

// ---------------------------------------------------------------------------
// TF32 qkv GEMM with direct bf16 outputs (qT/kT transposed, vbf row-major).
// grid (32, 6, BATCH): blockIdx.y -> {q0,q1,k0,k1,v0,v1} 128-row slabs.
// ---------------------------------------------------------------------------
__global__ __launch_bounds__(256, 2) void tf32_qkv_kernel(
    const float* __restrict__ A, const float* __restrict__ B,
    __nv_bfloat16* __restrict__ qT, __nv_bfloat16* __restrict__ kT,
    __nv_bfloat16* __restrict__ vbf, long sB,
    const float* __restrict__ bias)
{
    extern __shared__ char smem[];
    const uint32_t sb = smem_u32(smem);
    const int tid = threadIdx.x;
    const int wid = tid >> 5, lane = tid & 31;
    const int wm = wid & 3, wn = wid >> 2;
    const int z = blockIdx.z;
    const int bm = blockIdx.y * 128, bn = blockIdx.x * 128;
    const int which = blockIdx.y >> 1, half = blockIdx.y & 1;
    A += (size_t)bm * 256;
    B += (size_t)z * sB;

    float acc[2][8][4];
    #pragma unroll
    for (int mt = 0; mt < 2; mt++)
        #pragma unroll
        for (int nt = 0; nt < 8; nt++)
            #pragma unroll
            for (int e = 0; e < 4; e++) acc[mt][nt][e] = 0.f;

    tf_stage_a(sb, A, 256, 0, tid);
    tf_stage_kn(sb + TF_ASTG, B, 0, bn, tid);
    CP_COMMIT();

    for (int s = 0; s < 8; s++) {
        if (s + 1 < 8) {
            const uint32_t nb = sb + ((s + 1) & 1) * TF_STAGE;
            tf_stage_a(nb, A, 256, (s + 1) << 5, tid);
            tf_stage_kn(nb + TF_ASTG, B, (s + 1) << 5, bn, tid);
            CP_COMMIT();
            CP_WAIT(1);
        } else {
            CP_WAIT(0);
        }
        __syncthreads();

        const float* cA = (const float*)(smem + (s & 1) * TF_STAGE);
        const float* cB = (const float*)(smem + (s & 1) * TF_STAGE + TF_ASTG);
        #pragma unroll
        for (int ks = 0; ks < 4; ks++) {
            const int kk = ks * 8;
            uint32_t a[2][4];
            #pragma unroll
            for (int mt = 0; mt < 2; mt++) {
                const int m = wm * 32 + mt * 16 + (lane >> 2);
                const float* p = cA + m * TF_APITCH + kk + (lane & 3);
                a[mt][0] = __float_as_uint(p[0]);
                a[mt][1] = __float_as_uint(p[8 * TF_APITCH]);
                a[mt][2] = __float_as_uint(p[4]);
                a[mt][3] = __float_as_uint(p[8 * TF_APITCH + 4]);
            }
            #pragma unroll
            for (int nt = 0; nt < 8; nt++) {
                const int n = wn * 64 + nt * 8 + (lane >> 2);
                const float* p = cB + (kk + (lane & 3)) * TF_BPITCH + n;
                const uint32_t b0 = __float_as_uint(p[0]);
                const uint32_t b1 = __float_as_uint(p[4 * TF_BPITCH]);
                mma1688_tf32(acc[0][nt], a[0], b0, b1);
                mma1688_tf32(acc[1][nt], a[1], b0, b1);
            }
        }
        __syncthreads();
    }

    const int r0l = wm * 32 + (lane >> 2);   // local row (mt adds 16)
    if (which == 2) {
        // V: direct bf16 store, row-major [C][HW]
        __nv_bfloat16* vo = vbf + (size_t)z * CDIM * HW;
        #pragma unroll
        for (int mt = 0; mt < 2; mt++) {
            const int rl = r0l + mt * 16;
            const float bb0 = bias[bm + rl], bb1 = bias[bm + rl + 8];
            const int ch0 = half * 128 + rl;
            #pragma unroll
            for (int nt = 0; nt < 8; nt++) {
                const int col = bn + wn * 64 + nt * 8 + (lane & 3) * 2;
                __nv_bfloat162 v0 = __floats2bfloat162_rn(acc[mt][nt][0] + bb0,
                                                          acc[mt][nt][1] + bb0);
                __nv_bfloat162 v1 = __floats2bfloat162_rn(acc[mt][nt][2] + bb1,
                                                          acc[mt][nt][3] + bb1);
                *(__nv_bfloat162*)(vo + (size_t)ch0 * HW + col) = v0;
                *(__nv_bfloat162*)(vo + (size_t)(ch0 + 8) * HW + col) = v1;
            }
        }
    } else {
        // Q/K: stage [n][m] bf16 (pitch 136), then coalesced transposed store
        __nv_bfloat16* st = (__nv_bfloat16*)smem;
        #pragma unroll
        for (int mt = 0; mt < 2; mt++) {
            const int rl = r0l + mt * 16;
            const float bb0 = bias[bm + rl], bb1 = bias[bm + rl + 8];
            #pragma unroll
            for (int nt = 0; nt < 8; nt++) {
                const int col = wn * 64 + nt * 8 + (lane & 3) * 2;
                st[(col)     * 136 + rl]     = __float2bfloat16(acc[mt][nt][0] + bb0);
                st[(col + 1) * 136 + rl]     = __float2bfloat16(acc[mt][nt][1] + bb0);
                st[(col)     * 136 + rl + 8] = __float2bfloat16(acc[mt][nt][2] + bb1);
                st[(col + 1) * 136 + rl + 8] = __float2bfloat16(acc[mt][nt][3] + bb1);
            }
        }
        __syncthreads();
        __nv_bfloat16* dst = (which ? kT : qT) + (size_t)z * HW * CDIM + half * 128;
        #pragma unroll
        for (int i = 0; i < 8; i++) {
            const int f = tid + i * 256;
            const int n = f >> 4, u = f & 15;
            uint4 v = *(uint4*)(st + n * 136 + u * 8);
            *(uint4*)(dst + (size_t)(bn + n) * CDIM + u * 8) = v;
        }
    }
}

// ---------------------------------------------------------------------------
// FA2 flash attention (unchanged from R7)
// ---------------------------------------------------------------------------
#define FB_QPITCH 528
#define FB_VPITCH 144
#define FB_QSZ (128 * FB_QPITCH)
#define FB_K0 FB_QSZ
#define FB_KSZ (64 * FB_QPITCH)
#define FB_V0 (FB_K0 + 2 * FB_KSZ)
#define FB_VSZ (256 * FB_VPITCH)
#define FB_SMEM (FB_V0 + 2 * FB_VSZ)
#define FB_OPITCH 132

__device__ __forceinline__ void fb_stage_kv(
    uint32_t sb, const __nv_bfloat16* __restrict__ kT,
    const __nv_bfloat16* __restrict__ vbf, int kv0, int buf, int tid)
{
    const uint32_t kd = sb + FB_K0 + buf * FB_KSZ;
    const uint32_t vd = sb + FB_V0 + buf * FB_VSZ;
    #pragma unroll
    for (int i = 0; i < 8; i++) {
        const int ch = tid + i * 256;
        const int r = ch >> 5, s = ch & 31;
        cp16(kd + r * FB_QPITCH + s * 16, kT + (size_t)(kv0 + r) * CDIM + s * 8);
    }
    #pragma unroll
    for (int i = 0; i < 8; i++) {
        const int ch = tid + i * 256;
        const int r = ch >> 3, s = ch & 7;
        cp16(vd + r * FB_VPITCH + s * 16, vbf + (size_t)r * HW + kv0 + s * 8);
    }
}

__global__ __launch_bounds__(256, 1) void flash2_kernel(
    const __nv_bfloat16* __restrict__ qT, const __nv_bfloat16* __restrict__ kT,
    const __nv_bfloat16* __restrict__ vbf, float* __restrict__ O)
{
    extern __shared__ char smem[];
    const uint32_t sb = smem_u32(smem);
    const int tid = threadIdx.x, lane = tid & 31, wid = tid >> 5;
    const int z = blockIdx.y;
    const int bm = blockIdx.x * 128;
    qT  += (size_t)z * HW * CDIM + (size_t)bm * CDIM;
    kT  += (size_t)z * HW * CDIM;
    vbf += (size_t)z * CDIM * HW;
    O   += (size_t)z * CDIM * HW;

    #pragma unroll
    for (int i = 0; i < 16; i++) {
        const int ch = tid + i * 256;
        const int r = ch >> 5, s = ch & 31;
        cp16(sb + r * FB_QPITCH + s * 16, qT + (size_t)r * CDIM + s * 8);
    }
    CP_COMMIT();
    fb_stage_kv(sb, kT, vbf, 0, 0, tid);
    CP_COMMIT();

    float o[32][4];
    #pragma unroll
    for (int nt = 0; nt < 32; nt++)
        o[nt][0] = o[nt][1] = o[nt][2] = o[nt][3] = 0.f;
    float m0 = -1e30f, m1 = -1e30f, l0 = 0.f, l1 = 0.f;

    const int r_lo = lane >> 2;
    const int qrow = wid * 16;
    const int a_r  = lane & 15;
    const int a_kc = (lane >> 4) << 3;
    const int b_r  = (lane & 7) + ((lane >> 4) << 3);
    const int b_kc = ((lane >> 3) & 1) << 3;

    const int NI = HW / 64;
    for (int it = 0; it < NI; it++) {
        if (it + 1 < NI) {
            fb_stage_kv(sb, kT, vbf, (it + 1) * 64, (it + 1) & 1, tid);
            CP_COMMIT();
            CP_WAIT(1);
        } else {
            CP_WAIT(0);
        }
        __syncthreads();

        const uint32_t kb = sb + FB_K0 + (it & 1) * FB_KSZ;
        const uint32_t vb = sb + FB_V0 + (it & 1) * FB_VSZ;

        float s_[8][4];
        #pragma unroll
        for (int nt = 0; nt < 8; nt++)
            s_[nt][0] = s_[nt][1] = s_[nt][2] = s_[nt][3] = 0.f;
        #pragma unroll
        for (int ks = 0; ks < 16; ks++) {
            const int kk = ks * 16;
            uint32_t a[4];
            ldsm4(a[0], a[1], a[2], a[3],
                  sb + (qrow + a_r) * FB_QPITCH + (kk + a_kc) * 2);
            #pragma unroll
            for (int p = 0; p < 4; p++) {
                uint32_t b0, b1, b2, b3;
                ldsm4(b0, b1, b2, b3, kb + (p * 16 + b_r) * FB_QPITCH + (kk + b_kc) * 2);
                mma16816(s_[2 * p], a, b0, b1);
                mma16816(s_[2 * p + 1], a, b2, b3);
            }
        }

        float mx0 = -1e30f, mx1 = -1e30f;
        #pragma unroll
        for (int nt = 0; nt < 8; nt++) {
            mx0 = fmaxf(mx0, fmaxf(s_[nt][0], s_[nt][1]));
            mx1 = fmaxf(mx1, fmaxf(s_[nt][2], s_[nt][3]));
        }
        mx0 = fmaxf(mx0, __shfl_xor_sync(0xffffffff, mx0, 1));
        mx0 = fmaxf(mx0, __shfl_xor_sync(0xffffffff, mx0, 2));
        mx1 = fmaxf(mx1, __shfl_xor_sync(0xffffffff, mx1, 1));
        mx1 = fmaxf(mx1, __shfl_xor_sync(0xffffffff, mx1, 2));
        mx0 *= 0.0625f; mx1 *= 0.0625f;
        const float mn0 = fmaxf(m0, mx0), mn1 = fmaxf(m1, mx1);
        const float al0 = __expf(m0 - mn0), al1 = __expf(m1 - mn1);
        m0 = mn0; m1 = mn1;

        uint32_t p_[8][2];
        float sum0 = 0.f, sum1 = 0.f;
        #pragma unroll
        for (int nt = 0; nt < 8; nt++) {
            const float p0 = __expf(fmaf(s_[nt][0], 0.0625f, -m0));
            const float p1 = __expf(fmaf(s_[nt][1], 0.0625f, -m0));
            const float p2 = __expf(fmaf(s_[nt][2], 0.0625f, -m1));
            const float p3 = __expf(fmaf(s_[nt][3], 0.0625f, -m1));
            sum0 += p0 + p1; sum1 += p2 + p3;
            __nv_bfloat162 lo = __floats2bfloat162_rn(p0, p1);
            __nv_bfloat162 hi = __floats2bfloat162_rn(p2, p3);
            p_[nt][0] = *(uint32_t*)&lo;
            p_[nt][1] = *(uint32_t*)&hi;
        }
        sum0 += __shfl_xor_sync(0xffffffff, sum0, 1);
        sum0 += __shfl_xor_sync(0xffffffff, sum0, 2);
        sum1 += __shfl_xor_sync(0xffffffff, sum1, 1);
        sum1 += __shfl_xor_sync(0xffffffff, sum1, 2);
        l0 = l0 * al0 + sum0;
        l1 = l1 * al1 + sum1;

        #pragma unroll
        for (int nt = 0; nt < 32; nt++) {
            o[nt][0] *= al0; o[nt][1] *= al0;
            o[nt][2] *= al1; o[nt][3] *= al1;
        }
        #pragma unroll
        for (int kbs = 0; kbs < 4; kbs++) {
            uint32_t a[4] = { p_[2 * kbs][0], p_[2 * kbs][1],
                              p_[2 * kbs + 1][0], p_[2 * kbs + 1][1] };
            #pragma unroll
            for (int p = 0; p < 16; p++) {
                uint32_t b0, b1, b2, b3;
                ldsm4(b0, b1, b2, b3,
                      vb + (p * 16 + b_r) * FB_VPITCH + (kbs * 16 + b_kc) * 2);
                mma16816(o[2 * p], a, b0, b1);
                mma16816(o[2 * p + 1], a, b2, b3);
            }
        }
        __syncthreads();
    }

    const float i0 = 1.f / l0, i1 = 1.f / l1;
    float* os = (float*)(smem + FB_K0);
    #pragma unroll
    for (int nt = 0; nt < 32; nt++) {
        const int c = nt * 8 + (lane & 3) * 2;
        const int q = qrow + r_lo;
        os[c * FB_OPITCH + q]           = tf32r(o[nt][0] * i0);
        os[(c + 1) * FB_OPITCH + q]     = tf32r(o[nt][1] * i0);
        os[c * FB_OPITCH + q + 8]       = tf32r(o[nt][2] * i1);
        os[(c + 1) * FB_OPITCH + q + 8] = tf32r(o[nt][3] * i1);
    }
    __syncthreads();
    #pragma unroll
    for (int i = 0; i < 32; i++) {
        const int f = tid + i * 256;
        const int r = f >> 5, cq = (f & 31) * 4;
        float4 v = *(float4*)(os + r * FB_OPITCH + cq);
        *(float4*)(O + (size_t)r * HW + bm + cq) = v;
    }
}

// ---------------------------------------------------------------------------
// Weight prep kernels
// ---------------------------------------------------------------------------
__global__ __launch_bounds__(256) void tf32_round_kernel(
    const float* __restrict__ in, float* __restrict__ out, int n4)
{
    const int i = blockIdx.x * 256 + threadIdx.x;
    if (i < n4) {
        float4 v = ((const float4*)in)[i];
        v.x = tf32r(v.x); v.y = tf32r(v.y); v.z = tf32r(v.z); v.w = tf32r(v.w);
        ((float4*)out)[i] = v;
    }
}
// permute conv weights [m][ci*9+tap] -> [m][chunk][tap][ci32] (+tf32 round)
__global__ __launch_bounds__(256) void permw_kernel(
    const float* __restrict__ w, float* __restrict__ out)
{
    const int i = blockIdx.x * 256 + threadIdx.x;   // 589824 total
    const int m = i / 2304, k = i - m * 2304;
    const int cig = k / 9, t = k - cig * 9;
    const int c = cig >> 5, ci = cig & 31;
    out[m * 2304 + c * 288 + t * 32 + ci] = tf32r(w[i]);
}

// ---------------------------------------------------------------------------
// GroupNorm (+ optional SiLU, + optional tf32 rounding)
// ---------------------------------------------------------------------------
__global__ __launch_bounds__(256) void groupnorm_kernel(
    const float* __restrict__ in, float* __restrict__ out,
    const float* __restrict__ sc, const float* __restrict__ bi,
    int do_silu, int do_round)
{
    __shared__ float s_sum[256], s_sq[256];
    __shared__ float s_stats[2];
    const int t = threadIdx.x;
    const int bg = blockIdx.x;
    const size_t base = (size_t)bg * 32768;
    const int g = bg & 31;

    float sum = 0.f, sq = 0.f;
    for (int i = t * 4; i < 32768; i += 1024) {
        float4 v = *(const float4*)&in[base + i];
        sum += v.x + v.y + v.z + v.w;
        sq  += v.x*v.x + v.y*v.y + v.z*v.z + v.w*v.w;
    }
    s_sum[t] = sum; s_sq[t] = sq;
    __syncthreads();
    for (int s = 128; s > 0; s >>= 1) {
        if (t < s) { s_sum[t] += s_sum[t + s]; s_sq[t] += s_sq[t + s]; }
        __syncthreads();
    }
    if (t == 0) {
        float mean = s_sum[0] * (1.f / 32768.f);
        float var  = s_sq[0] * (1.f / 32768.f) - mean * mean;
        s_stats[0] = mean;
        s_stats[1] = rsqrtf(var + 1e-5f);
    }
    __syncthreads();
    const float mean = s_stats[0], rstd = s_stats[1];

    for (int i = t * 4; i < 32768; i += 1024) {
        const int c = (g << 3) + (i >> 12);
        const float a = sc[c] * rstd;
        const float b2 = bi[c] - mean * a;
        float4 v = *(const float4*)&in[base + i];
        float4 o;
        o.x = v.x * a + b2; o.y = v.y * a + b2;
        o.z = v.z * a + b2; o.w = v.w * a + b2;
        if (do_silu) {
            o.x = o.x / (1.f + __expf(-o.x));
            o.y = o.y / (1.f + __expf(-o.y));
            o.z = o.z / (1.f + __expf(-o.z));
            o.w = o.w / (1.f + __expf(-o.w));
        }
        if (do_round) {
            o.x = tf32r(o.x); o.y = tf32r(o.y);
            o.z = tf32r(o.z); o.w = tf32r(o.w);
        }
        *(float4*)&out[base + i] = o;
    }
}

// ---------------------------------------------------------------------------
// time-MLP
// ---------------------------------------------------------------------------
__global__ __launch_bounds__(256) void mlp_kernel(
    const float* __restrict__ te, const float* __restrict__ w,
    const float* __restrict__ mb, float* __restrict__ temb)
{
    __shared__ float s[TDIM];
    const int b = blockIdx.x, t = threadIdx.x;
    for (int i = t; i < TDIM; i += 256) {
        float v = te[b * TDIM + i];
        s[i] = v / (1.f + __expf(-v));
    }
    __syncthreads();
    float acc = 0.f;
    for (int k = 0; k < TDIM; k++) acc = fmaf(s[k], w[k * CDIM + t], acc);
    temb[b * CDIM + t] = acc + mb[t];
}

// ---------------------------------------------------------------------------
// Launch
// ---------------------------------------------------------------------------
extern "C" void kernel_launch(void* const* d_in, const int* in_sizes, int n_in,
                              void* d_out, int out_size)
{
    const float* x        = (const float*)d_in[0];
    const float* time_emb = (const float*)d_in[1];
    const float* gn1_s    = (const float*)d_in[2];
    const float* gn1_b    = (const float*)d_in[3];
    const float* conv1_w  = (const float*)d_in[4];
    const float* conv1_b  = (const float*)d_in[5];
    const float* mlp_w    = (const float*)d_in[6];
    const float* mlp_b    = (const float*)d_in[7];
    const float* gn2_s    = (const float*)d_in[8];
    const float* gn2_b    = (const float*)d_in[9];
    const float* conv2_w  = (const float*)d_in[10];
    const float* conv2_b  = (const float*)d_in[11];
    const float* an_s     = (const float*)d_in[12];
    const float* an_b     = (const float*)d_in[13];
    const float* qkv_w    = (const float*)d_in[14];
    const float* qkv_b    = (const float*)d_in[15];
    const float* out_w    = (const float*)d_in[16];
    const float* out_b    = (const float*)d_in[17];
    float* out = (float*)d_out;

    float *bufA, *bufB, *temb, *w1p, *w2p, *wqr, *wor;
    __nv_bfloat16 *qT, *kT, *vbf;
    cudaGetSymbolAddress((void**)&bufA, g_bufA);
    cudaGetSymbolAddress((void**)&bufB, g_bufB);
    cudaGetSymbolAddress((void**)&temb, g_temb);
    cudaGetSymbolAddress((void**)&w1p,  g_w1p);
    cudaGetSymbolAddress((void**)&w2p,  g_w2p);
    cudaGetSymbolAddress((void**)&wqr,  g_wqr);
    cudaGetSymbolAddress((void**)&wor,  g_wor);
    cudaGetSymbolAddress((void**)&qT,   g_qT);
    cudaGetSymbolAddress((void**)&kT,   g_kT);
    cudaGetSymbolAddress((void**)&vbf,  g_vbf);

    cudaFuncSetAttribute(tf32_conv_kernel,
                         cudaFuncAttributeMaxDynamicSharedMemorySize, CV_SMEM);
    cudaFuncSetAttribute(tf32_gemm_kernel,
                         cudaFuncAttributeMaxDynamicSharedMemorySize, TF_SMEM);
    cudaFuncSetAttribute(tf32_qkv_kernel,
                         cudaFuncAttributeMaxDynamicSharedMemorySize, TF_SMEM);
    cudaFuncSetAttribute(flash2_kernel,
                         cudaFuncAttributeMaxDynamicSharedMemorySize, FB_SMEM);

    const long sAct = (long)CDIM * HW;

    // weight prep
    permw_kernel<<<2304, 256>>>(conv1_w, w1p);
    permw_kernel<<<2304, 256>>>(conv2_w, w2p);
    tf32_round_kernel<<<192, 256>>>(qkv_w, wqr, 3 * CDIM * CDIM / 4);
    tf32_round_kernel<<<64, 256>>>(out_w, wor, CDIM * CDIM / 4);

    mlp_kernel<<<BATCH, 256>>>(time_emb, mlp_w, mlp_b, temb);

    // t1 = silu(gn1(x)) [tf32-rounded]
    groupnorm_kernel<<<BATCH * 32, 256>>>(x, bufA, gn1_s, gn1_b, 1, 1);
    // h1 = conv1(t1) + b + temb
    tf32_conv_kernel<<<dim3(32, 2, BATCH), 256, CV_SMEM>>>(
        w1p, bufA, bufB, sAct, sAct, conv1_b, temb, nullptr);
    // t2 = silu(gn2(h1)) [tf32-rounded]
    groupnorm_kernel<<<BATCH * 32, 256>>>(bufB, bufA, gn2_s, gn2_b, 1, 1);
    // xr = conv2(t2) + b + x
    tf32_conv_kernel<<<dim3(32, 2, BATCH), 256, CV_SMEM>>>(
        w2p, bufA, bufB, sAct, sAct, conv2_b, nullptr, x);
    // a = gn_an(xr) [tf32-rounded]
    groupnorm_kernel<<<BATCH * 32, 256>>>(bufB, bufA, an_s, an_b, 0, 1);
    // qkv -> qT/kT/vbf bf16 directly
    tf32_qkv_kernel<<<dim3(32, 6, BATCH), 256, TF_SMEM>>>(
        wqr, bufA, qT, kT, vbf, sAct, qkv_b);

    // FA2 fused attention: O (tf32-rounded, [C][HW]) -> bufA
    flash2_kernel<<<dim3(HW / 128, BATCH), 256, FB_SMEM>>>(qT, kT, vbf, bufA);

    // out = W_out @ O + out_b + xr
    tf32_gemm_kernel<<<dim3(32, 2, BATCH), 256, TF_SMEM>>>(
        wor, bufA, out, CDIM, CDIM, sAct, sAct, out_b, bufB);
}

// round 9
// speedup vs baseline: 1.4387x; 1.0000x over previous
#include <cuda_runtime.h>
#include <cuda_bf16.h>
#include <cstdint>
#include <cstddef>

#define BATCH 8
#define CDIM 256
#define HW 4096
#define TDIM 1024

// ---------------------------------------------------------------------------
// Static scratch (allocation forbidden)
// ---------------------------------------------------------------------------
__device__ float g_bufA[(size_t)BATCH * CDIM * HW];
__device__ float g_bufB[(size_t)BATCH * CDIM * HW];
__device__ float g_temb[BATCH * CDIM];
__device__ __nv_bfloat16 g_qT [(size_t)BATCH * HW * CDIM];
__device__ __nv_bfloat16 g_kT [(size_t)BATCH * HW * CDIM];
__device__ __nv_bfloat16 g_vbf[(size_t)BATCH * CDIM * HW];
__device__ float g_w1p[CDIM * CDIM * 9];     // permuted [m][chunk][tap][ci32]
__device__ float g_w2p[CDIM * CDIM * 9];
__device__ float g_wqr[3 * CDIM * CDIM];
__device__ float g_wor[CDIM * CDIM];

// ---------------------------------------------------------------------------
// PTX helpers
// ---------------------------------------------------------------------------
__device__ __forceinline__ uint32_t smem_u32(const void* p) {
    uint32_t a;
    asm("{ .reg .u64 t; cvta.to.shared.u64 t, %1; cvt.u32.u64 %0, t; }"
        : "=r"(a) : "l"(p));
    return a;
}
__device__ __forceinline__ void cp16(uint32_t dst, const void* src) {
    asm volatile("cp.async.cg.shared.global [%0], [%1], 16;" :: "r"(dst), "l"(src));
}
__device__ __forceinline__ void cp16_pred(uint32_t dst, const void* src, bool p) {
    int sz = p ? 16 : 0;
    asm volatile("cp.async.cg.shared.global [%0], [%1], 16, %2;"
                 :: "r"(dst), "l"(src), "r"(sz));
}
#define CP_COMMIT() asm volatile("cp.async.commit_group;" ::: "memory")
#define CP_WAIT(n)  asm volatile("cp.async.wait_group %0;" :: "n"(n) : "memory")

__device__ __forceinline__ void ldsm4(uint32_t& r0, uint32_t& r1,
                                      uint32_t& r2, uint32_t& r3, uint32_t addr) {
    asm volatile("ldmatrix.sync.aligned.m8n8.x4.shared.b16 {%0,%1,%2,%3}, [%4];"
                 : "=r"(r0), "=r"(r1), "=r"(r2), "=r"(r3) : "r"(addr));
}
__device__ __forceinline__ void mma16816(float* c, const uint32_t* a,
                                         uint32_t b0, uint32_t b1) {
    asm volatile(
        "mma.sync.aligned.m16n8k16.row.col.f32.bf16.bf16.f32 "
        "{%0,%1,%2,%3}, {%4,%5,%6,%7}, {%8,%9}, {%0,%1,%2,%3};"
        : "+f"(c[0]), "+f"(c[1]), "+f"(c[2]), "+f"(c[3])
        : "r"(a[0]), "r"(a[1]), "r"(a[2]), "r"(a[3]), "r"(b0), "r"(b1));
}
__device__ __forceinline__ void mma1688_tf32(float* c, const uint32_t* a,
                                             uint32_t b0, uint32_t b1) {
    asm volatile(
        "mma.sync.aligned.m16n8k8.row.col.f32.tf32.tf32.f32 "
        "{%0,%1,%2,%3}, {%4,%5,%6,%7}, {%8,%9}, {%0,%1,%2,%3};"
        : "+f"(c[0]), "+f"(c[1]), "+f"(c[2]), "+f"(c[3])
        : "r"(a[0]), "r"(a[1]), "r"(a[2]), "r"(a[3]), "r"(b0), "r"(b1));
}
__device__ __forceinline__ float tf32r(float x) {
    uint32_t u;
    asm("cvt.rna.tf32.f32 %0, %1;" : "=r"(u) : "f"(x));
    return __uint_as_float(u);
}

// ---------------------------------------------------------------------------
// TF32 3x3 conv kernel (raw-tile loader, 9 shifted-view taps).
// C[m][n] = sum_{ci,tap} Wp[m][c][tap][ci] * X[ci][y(n)+dy][x(n)+dx]
// Wp: permuted weights [256m][8 chunk][9 tap][32 ci].
// X:  [256 ci][64][64] fp32 (tf32-rounded), batch stride sB.
// Tile 128m x 128n (= 2 image rows). 8 warps (4m x 2n). BK per tap = 32 ci.
// Smem: raw B tile [32ci][4 rows][72 pitch] x2 buf + A slab [128][36] x2.
// grid (32, 2, BATCH), 256 threads.
// ---------------------------------------------------------------------------
#define CV_ROWW 72
#define CV_CIW 296                            // 4*72 + 8 (bank skew)
#define CV_BRAW (32 * CV_CIW * 4)             // 37888 B per buffer
#define CV_ABUF (128 * 36 * 4)                // 18432 B per buffer
#define CV_SMEM (2 * CV_BRAW + 2 * CV_ABUF)   // 112640

__device__ __forceinline__ void cv_stage_b_slice(
    uint32_t sb, const float* __restrict__ X, int chunk, int buf,
    int slice, int Y0, int tid)
{
    const int f = slice * 256 + tid;          // 0..2047
    const int ci = f >> 6, rr = f & 63;
    const int yy = rr >> 4, s2 = rr & 15;
    const int y = Y0 - 1 + yy;
    const bool valid = (unsigned)y < 64u;
    const uint32_t dst = sb + buf * CV_BRAW + (ci * CV_CIW + yy * CV_ROWW + 4 + s2 * 4) * 4;
    cp16_pred(dst, X + (size_t)(chunk * 32 + ci) * 4096 + y * 64 + s2 * 4, valid);
}
__device__ __forceinline__ void cv_stage_a(
    uint32_t sb, const float* __restrict__ Wp, int chunk, int tap, int buf, int tid)
{
    #pragma unroll
    for (int i = 0; i < 4; i++) {
        const int f = tid + i * 256;
        const int m = f >> 3, s = f & 7;
        cp16(sb + 2 * CV_BRAW + buf * CV_ABUF + (m * 36 + s * 4) * 4,
             Wp + (size_t)m * 2304 + chunk * 288 + tap * 32 + s * 4);
    }
}

__global__ __launch_bounds__(256, 2) void tf32_conv_kernel(
    const float* __restrict__ Wp, const float* __restrict__ X, float* __restrict__ C,
    long sB, long sC,
    const float* __restrict__ bias, const float* __restrict__ bias2,
    const float* __restrict__ res)
{
    extern __shared__ char smem[];
    const uint32_t sb = smem_u32(smem);
    const int tid = threadIdx.x;
    const int wid = tid >> 5, lane = tid & 31;
    const int wm = wid & 3, wn = wid >> 2;
    const int r4 = lane & 3, q4 = lane >> 2;
    const int z = blockIdx.z;
    const int bm = blockIdx.y * 128, bn = blockIdx.x * 128;
    const int Y0 = bn >> 6;
    Wp += (size_t)bm * 2304;
    X += (size_t)z * sB;
    C += (size_t)z * sC;
    const float* rp = res ? res + (size_t)z * sC : nullptr;

    // zero halo columns (x=3, x=68) of both raw buffers
    #pragma unroll
    for (int j = 0; j < 2; j++) {
        const int idx = tid + j * 256;
        const int b = idx >> 8, r = idx & 255;
        const int ci = r >> 3, yy = (r >> 1) & 3, side = r & 1;
        ((float*)smem)[b * (CV_BRAW / 4) + ci * CV_CIW + yy * CV_ROWW + (side ? 68 : 3)] = 0.f;
    }

    // prologue: full B(chunk 0) + A(0,0)
    #pragma unroll
    for (int s = 0; s < 8; s++) cv_stage_b_slice(sb, X, 0, 0, s, Y0, tid);
    cv_stage_a(sb, Wp, 0, 0, 0, tid);
    CP_COMMIT();

    float acc[2][8][4];
    #pragma unroll
    for (int mt = 0; mt < 2; mt++)
        #pragma unroll
        for (int nt = 0; nt < 8; nt++)
            #pragma unroll
            for (int e = 0; e < 4; e++) acc[mt][nt][e] = 0.f;

    int iter = 0;
    for (int c = 0; c < 8; c++) {
        #pragma unroll
        for (int t = 0; t < 9; t++) {
            CP_WAIT(0);
            __syncthreads();
            // prefetch next A slab + one slice of next chunk's raw B
            if (!(c == 7 && t == 8)) {
                const int c2 = (t == 8) ? c + 1 : c;
                const int t2 = (t == 8) ? 0 : t + 1;
                cv_stage_a(sb, Wp, c2, t2, (iter + 1) & 1, tid);
                if (c < 7 && t < 8) cv_stage_b_slice(sb, X, c + 1, (c + 1) & 1, t, Y0, tid);
                CP_COMMIT();
            }
            // compute tap t of chunk c
            const int dy = t / 3 - 1, dx = t - (t / 3) * 3 - 1;
            const float* aB = (const float*)(smem + 2 * CV_BRAW + (iter & 1) * CV_ABUF);
            const float* bB = (const float*)(smem + (c & 1) * CV_BRAW);
            const int bofs = (wn + dy + 1) * CV_ROWW + dx + 4 + q4;
            #pragma unroll
            for (int ks = 0; ks < 4; ks++) {
                const int kk = ks * 8;
                uint32_t a[2][4];
                #pragma unroll
                for (int mt = 0; mt < 2; mt++) {
                    const int m = wm * 32 + mt * 16 + q4;
                    const float* p = aB + m * 36 + kk + r4;
                    a[mt][0] = __float_as_uint(p[0]);
                    a[mt][1] = __float_as_uint(p[8 * 36]);
                    a[mt][2] = __float_as_uint(p[4]);
                    a[mt][3] = __float_as_uint(p[8 * 36 + 4]);
                }
                const int cib = (kk + r4) * CV_CIW;
                #pragma unroll
                for (int nt = 0; nt < 8; nt++) {
                    const uint32_t b0 = __float_as_uint(bB[cib + bofs + nt * 8]);
                    const uint32_t b1 = __float_as_uint(bB[cib + 4 * CV_CIW + bofs + nt * 8]);
                    mma1688_tf32(acc[0][nt], a[0], b0, b1);
                    mma1688_tf32(acc[1][nt], a[1], b0, b1);
                }
            }
            iter++;
        }
    }

    // epilogue
    #pragma unroll
    for (int mt = 0; mt < 2; mt++) {
        const int r0 = bm + wm * 32 + mt * 16 + q4;
        float bb0 = 0.f, bb1 = 0.f;
        if (bias)  { bb0 = bias[r0]; bb1 = bias[r0 + 8]; }
        if (bias2) { bb0 += bias2[z * 256 + r0]; bb1 += bias2[z * 256 + r0 + 8]; }
        #pragma unroll
        for (int nt = 0; nt < 8; nt++) {
            const int col = bn + wn * 64 + nt * 8 + r4 * 2;
            const size_t o0 = (size_t)r0 * 4096 + col;
            const size_t o1 = o0 + (size_t)8 * 4096;
            float2 v0 = { acc[mt][nt][0] + bb0, acc[mt][nt][1] + bb0 };
            float2 v1 = { acc[mt][nt][2] + bb1, acc[mt][nt][3] + bb1 };
            if (rp) {
                float2 u0 = *(const float2*)(rp + o0);
                float2 u1 = *(const float2*)(rp + o1);
                v0.x += u0.x; v0.y += u0.y; v1.x += u1.x; v1.y += u1.y;
            }
            *(float2*)(C + o0) = v0;
            *(float2*)(C + o1) = v1;
        }
    }
}

// ---------------------------------------------------------------------------
// TF32 GEMM (out projection): C = A*B + bias + res
// ---------------------------------------------------------------------------
#define TF_APITCH 36
#define TF_BPITCH 132
#define TF_ASTG (128 * TF_APITCH * 4)
#define TF_BSTG (32 * TF_BPITCH * 4)
#define TF_STAGE (TF_ASTG + TF_BSTG)
#define TF_SMEM (2 * TF_STAGE)

__device__ __forceinline__ void tf_stage_a(
    uint32_t sbA, const float* __restrict__ A, int K, int k0, int tid)
{
    #pragma unroll
    for (int i = 0; i < 4; i++) {
        const int v = tid + i * 256;
        const int r = v >> 3, sub = v & 7;
        cp16(sbA + (r * TF_APITCH + sub * 4) * 4, A + (size_t)r * K + k0 + sub * 4);
    }
}
__device__ __forceinline__ void tf_stage_kn(
    uint32_t sbB, const float* __restrict__ B, int k0, int bn, int tid)
{
    #pragma unroll
    for (int i = 0; i < 4; i++) {
        const int v = tid + i * 256;
        const int k = v >> 5, sub = v & 31;
        cp16(sbB + (k * TF_BPITCH + sub * 4) * 4,
             B + (size_t)(k0 + k) * 4096 + bn + sub * 4);
    }
}

// shared mainloop body macro-free: plain function for out-GEMM
__global__ __launch_bounds__(256, 2) void tf32_gemm_kernel(
    const float* __restrict__ A, const float* __restrict__ B, float* __restrict__ C,
    int M, int K, long sB, long sC,
    const float* __restrict__ bias, const float* __restrict__ res)
{
    extern __shared__ char smem[];
    const uint32_t sb = smem_u32(smem);
    const int tid = threadIdx.x;
    const int wid = tid >> 5, lane = tid & 31;
    const int wm = wid & 3, wn = wid >> 2;
    const int z = blockIdx.z;
    const int bm = blockIdx.y * 128, bn = blockIdx.x * 128;
    A += (size_t)bm * K;
    B += (size_t)z * sB;
    C += (size_t)z * sC;
    const float* rp = res ? res + (size_t)z * sC : nullptr;

    float acc[2][8][4];
    #pragma unroll
    for (int mt = 0; mt < 2; mt++)
        #pragma unroll
        for (int nt = 0; nt < 8; nt++)
            #pragma unroll
            for (int e = 0; e < 4; e++) acc[mt][nt][e] = 0.f;

    const int S = K >> 5;
    tf_stage_a(sb, A, K, 0, tid);
    tf_stage_kn(sb + TF_ASTG, B, 0, bn, tid);
    CP_COMMIT();

    for (int s = 0; s < S; s++) {
        if (s + 1 < S) {
            const uint32_t nb = sb + ((s + 1) & 1) * TF_STAGE;
            tf_stage_a(nb, A, K, (s + 1) << 5, tid);
            tf_stage_kn(nb + TF_ASTG, B, (s + 1) << 5, bn, tid);
            CP_COMMIT();
            CP_WAIT(1);
        } else {
            CP_WAIT(0);
        }
        __syncthreads();

        const float* cA = (const float*)(smem + (s & 1) * TF_STAGE);
        const float* cB = (const float*)(smem + (s & 1) * TF_STAGE + TF_ASTG);
        #pragma unroll
        for (int ks = 0; ks < 4; ks++) {
            const int kk = ks * 8;
            uint32_t a[2][4];
            #pragma unroll
            for (int mt = 0; mt < 2; mt++) {
                const int m = wm * 32 + mt * 16 + (lane >> 2);
                const float* p = cA + m * TF_APITCH + kk + (lane & 3);
                a[mt][0] = __float_as_uint(p[0]);
                a[mt][1] = __float_as_uint(p[8 * TF_APITCH]);
                a[mt][2] = __float_as_uint(p[4]);
                a[mt][3] = __float_as_uint(p[8 * TF_APITCH + 4]);
            }
            #pragma unroll
            for (int nt = 0; nt < 8; nt++) {
                const int n = wn * 64 + nt * 8 + (lane >> 2);
                const float* p = cB + (kk + (lane & 3)) * TF_BPITCH + n;
                const uint32_t b0 = __float_as_uint(p[0]);
                const uint32_t b1 = __float_as_uint(p[4 * TF_BPITCH]);
                mma1688_tf32(acc[0][nt], a[0], b0, b1);
                mma1688_tf32(acc[1][nt], a[1], b0, b1);
            }
        }
        __syncthreads();
    }

    #pragma unroll
    for (int mt = 0; mt < 2; mt++) {
        const int r0 = bm + wm * 32 + mt * 16 + (lane >> 2);
        float bb0 = 0.f, bb1 = 0.f;
        if (bias) { bb0 = bias[r0]; bb1 = bias[r0 + 8]; }
        #pragma unroll
        for (int nt = 0; nt < 8; nt++) {
            const int col = bn + wn * 64 + nt * 8 + (lane & 3) * 2;
            const size_t o0 = (size_t)r0 * 4096 + col;
            const size_t o1 = o0 + (size_t)8 * 4096;
            float2 v0 = { acc[mt][nt][0] + bb0, acc[mt][nt][1] + bb0 };
            float2 v1 = { acc[mt][nt][2] + bb1, acc[mt][nt][3] + bb1 };
            if (rp) {
                float2 q0 = *(const float2*)(rp + o0);
                float2 q1 = *(const float2*)(rp + o1);
                v0.x += q0.x; v0.y += q0.y; v1.x += q1.x; v1.y += q1.y;
            }
            *(float2*)(C + o0) = v0;
            *(float2*)(C + o1) = v1;
        }
    }
}

// ---------------------------------------------------------------------------
// TF32 qkv GEMM with direct bf16 outputs (qT/kT transposed, vbf row-major).
// grid (32, 6, BATCH): blockIdx.y -> {q0,q1,k0,k1,v0,v1} 128-row slabs.
// ---------------------------------------------------------------------------
__global__ __launch_bounds__(256, 2) void tf32_qkv_kernel(
    const float* __restrict__ A, const float* __restrict__ B,
    __nv_bfloat16* __restrict__ qT, __nv_bfloat16* __restrict__ kT,
    __nv_bfloat16* __restrict__ vbf, long sB,
    const float* __restrict__ bias)
{
    extern __shared__ char smem[];
    const uint32_t sb = smem_u32(smem);
    const int tid = threadIdx.x;
    const int wid = tid >> 5, lane = tid & 31;
    const int wm = wid & 3, wn = wid >> 2;
    const int z = blockIdx.z;
    const int bm = blockIdx.y * 128, bn = blockIdx.x * 128;
    const int which = blockIdx.y >> 1, half = blockIdx.y & 1;
    A += (size_t)bm * 256;
    B += (size_t)z * sB;

    float acc[2][8][4];
    #pragma unroll
    for (int mt = 0; mt < 2; mt++)
        #pragma unroll
        for (int nt = 0; nt < 8; nt++)
            #pragma unroll
            for (int e = 0; e < 4; e++) acc[mt][nt][e] = 0.f;

    tf_stage_a(sb, A, 256, 0, tid);
    tf_stage_kn(sb + TF_ASTG, B, 0, bn, tid);
    CP_COMMIT();

    for (int s = 0; s < 8; s++) {
        if (s + 1 < 8) {
            const uint32_t nb = sb + ((s + 1) & 1) * TF_STAGE;
            tf_stage_a(nb, A, 256, (s + 1) << 5, tid);
            tf_stage_kn(nb + TF_ASTG, B, (s + 1) << 5, bn, tid);
            CP_COMMIT();
            CP_WAIT(1);
        } else {
            CP_WAIT(0);
        }
        __syncthreads();

        const float* cA = (const float*)(smem + (s & 1) * TF_STAGE);
        const float* cB = (const float*)(smem + (s & 1) * TF_STAGE + TF_ASTG);
        #pragma unroll
        for (int ks = 0; ks < 4; ks++) {
            const int kk = ks * 8;
            uint32_t a[2][4];
            #pragma unroll
            for (int mt = 0; mt < 2; mt++) {
                const int m = wm * 32 + mt * 16 + (lane >> 2);
                const float* p = cA + m * TF_APITCH + kk + (lane & 3);
                a[mt][0] = __float_as_uint(p[0]);
                a[mt][1] = __float_as_uint(p[8 * TF_APITCH]);
                a[mt][2] = __float_as_uint(p[4]);
                a[mt][3] = __float_as_uint(p[8 * TF_APITCH + 4]);
            }
            #pragma unroll
            for (int nt = 0; nt < 8; nt++) {
                const int n = wn * 64 + nt * 8 + (lane >> 2);
                const float* p = cB + (kk + (lane & 3)) * TF_BPITCH + n;
                const uint32_t b0 = __float_as_uint(p[0]);
                const uint32_t b1 = __float_as_uint(p[4 * TF_BPITCH]);
                mma1688_tf32(acc[0][nt], a[0], b0, b1);
                mma1688_tf32(acc[1][nt], a[1], b0, b1);
            }
        }
        __syncthreads();
    }

    const int r0l = wm * 32 + (lane >> 2);   // local row (mt adds 16)
    if (which == 2) {
        // V: direct bf16 store, row-major [C][HW]
        __nv_bfloat16* vo = vbf + (size_t)z * CDIM * HW;
        #pragma unroll
        for (int mt = 0; mt < 2; mt++) {
            const int rl = r0l + mt * 16;
            const float bb0 = bias[bm + rl], bb1 = bias[bm + rl + 8];
            const int ch0 = half * 128 + rl;
            #pragma unroll
            for (int nt = 0; nt < 8; nt++) {
                const int col = bn + wn * 64 + nt * 8 + (lane & 3) * 2;
                __nv_bfloat162 v0 = __floats2bfloat162_rn(acc[mt][nt][0] + bb0,
                                                          acc[mt][nt][1] + bb0);
                __nv_bfloat162 v1 = __floats2bfloat162_rn(acc[mt][nt][2] + bb1,
                                                          acc[mt][nt][3] + bb1);
                *(__nv_bfloat162*)(vo + (size_t)ch0 * HW + col) = v0;
                *(__nv_bfloat162*)(vo + (size_t)(ch0 + 8) * HW + col) = v1;
            }
        }
    } else {
        // Q/K: stage [n][m] bf16 (pitch 136), then coalesced transposed store
        __nv_bfloat16* st = (__nv_bfloat16*)smem;
        #pragma unroll
        for (int mt = 0; mt < 2; mt++) {
            const int rl = r0l + mt * 16;
            const float bb0 = bias[bm + rl], bb1 = bias[bm + rl + 8];
            #pragma unroll
            for (int nt = 0; nt < 8; nt++) {
                const int col = wn * 64 + nt * 8 + (lane & 3) * 2;
                st[(col)     * 136 + rl]     = __float2bfloat16(acc[mt][nt][0] + bb0);
                st[(col + 1) * 136 + rl]     = __float2bfloat16(acc[mt][nt][1] + bb0);
                st[(col)     * 136 + rl + 8] = __float2bfloat16(acc[mt][nt][2] + bb1);
                st[(col + 1) * 136 + rl + 8] = __float2bfloat16(acc[mt][nt][3] + bb1);
            }
        }
        __syncthreads();
        __nv_bfloat16* dst = (which ? kT : qT) + (size_t)z * HW * CDIM + half * 128;
        #pragma unroll
        for (int i = 0; i < 8; i++) {
            const int f = tid + i * 256;
            const int n = f >> 4, u = f & 15;
            uint4 v = *(uint4*)(st + n * 136 + u * 8);
            *(uint4*)(dst + (size_t)(bn + n) * CDIM + u * 8) = v;
        }
    }
}

// ---------------------------------------------------------------------------
// FA2 flash attention (unchanged from R7)
// ---------------------------------------------------------------------------
#define FB_QPITCH 528
#define FB_VPITCH 144
#define FB_QSZ (128 * FB_QPITCH)
#define FB_K0 FB_QSZ
#define FB_KSZ (64 * FB_QPITCH)
#define FB_V0 (FB_K0 + 2 * FB_KSZ)
#define FB_VSZ (256 * FB_VPITCH)
#define FB_SMEM (FB_V0 + 2 * FB_VSZ)
#define FB_OPITCH 132

__device__ __forceinline__ void fb_stage_kv(
    uint32_t sb, const __nv_bfloat16* __restrict__ kT,
    const __nv_bfloat16* __restrict__ vbf, int kv0, int buf, int tid)
{
    const uint32_t kd = sb + FB_K0 + buf * FB_KSZ;
    const uint32_t vd = sb + FB_V0 + buf * FB_VSZ;
    #pragma unroll
    for (int i = 0; i < 8; i++) {
        const int ch = tid + i * 256;
        const int r = ch >> 5, s = ch & 31;
        cp16(kd + r * FB_QPITCH + s * 16, kT + (size_t)(kv0 + r) * CDIM + s * 8);
    }
    #pragma unroll
    for (int i = 0; i < 8; i++) {
        const int ch = tid + i * 256;
        const int r = ch >> 3, s = ch & 7;
        cp16(vd + r * FB_VPITCH + s * 16, vbf + (size_t)r * HW + kv0 + s * 8);
    }
}

__global__ __launch_bounds__(256, 1) void flash2_kernel(
    const __nv_bfloat16* __restrict__ qT, const __nv_bfloat16* __restrict__ kT,
    const __nv_bfloat16* __restrict__ vbf, float* __restrict__ O)
{
    extern __shared__ char smem[];
    const uint32_t sb = smem_u32(smem);
    const int tid = threadIdx.x, lane = tid & 31, wid = tid >> 5;
    const int z = blockIdx.y;
    const int bm = blockIdx.x * 128;
    qT  += (size_t)z * HW * CDIM + (size_t)bm * CDIM;
    kT  += (size_t)z * HW * CDIM;
    vbf += (size_t)z * CDIM * HW;
    O   += (size_t)z * CDIM * HW;

    #pragma unroll
    for (int i = 0; i < 16; i++) {
        const int ch = tid + i * 256;
        const int r = ch >> 5, s = ch & 31;
        cp16(sb + r * FB_QPITCH + s * 16, qT + (size_t)r * CDIM + s * 8);
    }
    CP_COMMIT();
    fb_stage_kv(sb, kT, vbf, 0, 0, tid);
    CP_COMMIT();

    float o[32][4];
    #pragma unroll
    for (int nt = 0; nt < 32; nt++)
        o[nt][0] = o[nt][1] = o[nt][2] = o[nt][3] = 0.f;
    float m0 = -1e30f, m1 = -1e30f, l0 = 0.f, l1 = 0.f;

    const int r_lo = lane >> 2;
    const int qrow = wid * 16;
    const int a_r  = lane & 15;
    const int a_kc = (lane >> 4) << 3;
    const int b_r  = (lane & 7) + ((lane >> 4) << 3);
    const int b_kc = ((lane >> 3) & 1) << 3;

    const int NI = HW / 64;
    for (int it = 0; it < NI; it++) {
        if (it + 1 < NI) {
            fb_stage_kv(sb, kT, vbf, (it + 1) * 64, (it + 1) & 1, tid);
            CP_COMMIT();
            CP_WAIT(1);
        } else {
            CP_WAIT(0);
        }
        __syncthreads();

        const uint32_t kb = sb + FB_K0 + (it & 1) * FB_KSZ;
        const uint32_t vb = sb + FB_V0 + (it & 1) * FB_VSZ;

        float s_[8][4];
        #pragma unroll
        for (int nt = 0; nt < 8; nt++)
            s_[nt][0] = s_[nt][1] = s_[nt][2] = s_[nt][3] = 0.f;
        #pragma unroll
        for (int ks = 0; ks < 16; ks++) {
            const int kk = ks * 16;
            uint32_t a[4];
            ldsm4(a[0], a[1], a[2], a[3],
                  sb + (qrow + a_r) * FB_QPITCH + (kk + a_kc) * 2);
            #pragma unroll
            for (int p = 0; p < 4; p++) {
                uint32_t b0, b1, b2, b3;
                ldsm4(b0, b1, b2, b3, kb + (p * 16 + b_r) * FB_QPITCH + (kk + b_kc) * 2);
                mma16816(s_[2 * p], a, b0, b1);
                mma16816(s_[2 * p + 1], a, b2, b3);
            }
        }

        float mx0 = -1e30f, mx1 = -1e30f;
        #pragma unroll
        for (int nt = 0; nt < 8; nt++) {
            mx0 = fmaxf(mx0, fmaxf(s_[nt][0], s_[nt][1]));
            mx1 = fmaxf(mx1, fmaxf(s_[nt][2], s_[nt][3]));
        }
        mx0 = fmaxf(mx0, __shfl_xor_sync(0xffffffff, mx0, 1));
        mx0 = fmaxf(mx0, __shfl_xor_sync(0xffffffff, mx0, 2));
        mx1 = fmaxf(mx1, __shfl_xor_sync(0xffffffff, mx1, 1));
        mx1 = fmaxf(mx1, __shfl_xor_sync(0xffffffff, mx1, 2));
        mx0 *= 0.0625f; mx1 *= 0.0625f;
        const float mn0 = fmaxf(m0, mx0), mn1 = fmaxf(m1, mx1);
        const float al0 = __expf(m0 - mn0), al1 = __expf(m1 - mn1);
        m0 = mn0; m1 = mn1;

        uint32_t p_[8][2];
        float sum0 = 0.f, sum1 = 0.f;
        #pragma unroll
        for (int nt = 0; nt < 8; nt++) {
            const float p0 = __expf(fmaf(s_[nt][0], 0.0625f, -m0));
            const float p1 = __expf(fmaf(s_[nt][1], 0.0625f, -m0));
            const float p2 = __expf(fmaf(s_[nt][2], 0.0625f, -m1));
            const float p3 = __expf(fmaf(s_[nt][3], 0.0625f, -m1));
            sum0 += p0 + p1; sum1 += p2 + p3;
            __nv_bfloat162 lo = __floats2bfloat162_rn(p0, p1);
            __nv_bfloat162 hi = __floats2bfloat162_rn(p2, p3);
            p_[nt][0] = *(uint32_t*)&lo;
            p_[nt][1] = *(uint32_t*)&hi;
        }
        sum0 += __shfl_xor_sync(0xffffffff, sum0, 1);
        sum0 += __shfl_xor_sync(0xffffffff, sum0, 2);
        sum1 += __shfl_xor_sync(0xffffffff, sum1, 1);
        sum1 += __shfl_xor_sync(0xffffffff, sum1, 2);
        l0 = l0 * al0 + sum0;
        l1 = l1 * al1 + sum1;

        #pragma unroll
        for (int nt = 0; nt < 32; nt++) {
            o[nt][0] *= al0; o[nt][1] *= al0;
            o[nt][2] *= al1; o[nt][3] *= al1;
        }
        #pragma unroll
        for (int kbs = 0; kbs < 4; kbs++) {
            uint32_t a[4] = { p_[2 * kbs][0], p_[2 * kbs][1],
                              p_[2 * kbs + 1][0], p_[2 * kbs + 1][1] };
            #pragma unroll
            for (int p = 0; p < 16; p++) {
                uint32_t b0, b1, b2, b3;
                ldsm4(b0, b1, b2, b3,
                      vb + (p * 16 + b_r) * FB_VPITCH + (kbs * 16 + b_kc) * 2);
                mma16816(o[2 * p], a, b0, b1);
                mma16816(o[2 * p + 1], a, b2, b3);
            }
        }
        __syncthreads();
    }

    const float i0 = 1.f / l0, i1 = 1.f / l1;
    float* os = (float*)(smem + FB_K0);
    #pragma unroll
    for (int nt = 0; nt < 32; nt++) {
        const int c = nt * 8 + (lane & 3) * 2;
        const int q = qrow + r_lo;
        os[c * FB_OPITCH + q]           = tf32r(o[nt][0] * i0);
        os[(c + 1) * FB_OPITCH + q]     = tf32r(o[nt][1] * i0);
        os[c * FB_OPITCH + q + 8]       = tf32r(o[nt][2] * i1);
        os[(c + 1) * FB_OPITCH + q + 8] = tf32r(o[nt][3] * i1);
    }
    __syncthreads();
    #pragma unroll
    for (int i = 0; i < 32; i++) {
        const int f = tid + i * 256;
        const int r = f >> 5, cq = (f & 31) * 4;
        float4 v = *(float4*)(os + r * FB_OPITCH + cq);
        *(float4*)(O + (size_t)r * HW + bm + cq) = v;
    }
}

// ---------------------------------------------------------------------------
// Weight prep kernels
// ---------------------------------------------------------------------------
__global__ __launch_bounds__(256) void tf32_round_kernel(
    const float* __restrict__ in, float* __restrict__ out, int n4)
{
    const int i = blockIdx.x * 256 + threadIdx.x;
    if (i < n4) {
        float4 v = ((const float4*)in)[i];
        v.x = tf32r(v.x); v.y = tf32r(v.y); v.z = tf32r(v.z); v.w = tf32r(v.w);
        ((float4*)out)[i] = v;
    }
}
// permute conv weights [m][ci*9+tap] -> [m][chunk][tap][ci32] (+tf32 round)
__global__ __launch_bounds__(256) void permw_kernel(
    const float* __restrict__ w, float* __restrict__ out)
{
    const int i = blockIdx.x * 256 + threadIdx.x;   // 589824 total
    const int m = i / 2304, k = i - m * 2304;
    const int cig = k / 9, t = k - cig * 9;
    const int c = cig >> 5, ci = cig & 31;
    out[m * 2304 + c * 288 + t * 32 + ci] = tf32r(w[i]);
}

// ---------------------------------------------------------------------------
// GroupNorm (+ optional SiLU, + optional tf32 rounding)
// ---------------------------------------------------------------------------
__global__ __launch_bounds__(256) void groupnorm_kernel(
    const float* __restrict__ in, float* __restrict__ out,
    const float* __restrict__ sc, const float* __restrict__ bi,
    int do_silu, int do_round)
{
    __shared__ float s_sum[256], s_sq[256];
    __shared__ float s_stats[2];
    const int t = threadIdx.x;
    const int bg = blockIdx.x;
    const size_t base = (size_t)bg * 32768;
    const int g = bg & 31;

    float sum = 0.f, sq = 0.f;
    for (int i = t * 4; i < 32768; i += 1024) {
        float4 v = *(const float4*)&in[base + i];
        sum += v.x + v.y + v.z + v.w;
        sq  += v.x*v.x + v.y*v.y + v.z*v.z + v.w*v.w;
    }
    s_sum[t] = sum; s_sq[t] = sq;
    __syncthreads();
    for (int s = 128; s > 0; s >>= 1) {
        if (t < s) { s_sum[t] += s_sum[t + s]; s_sq[t] += s_sq[t + s]; }
        __syncthreads();
    }
    if (t == 0) {
        float mean = s_sum[0] * (1.f / 32768.f);
        float var  = s_sq[0] * (1.f / 32768.f) - mean * mean;
        s_stats[0] = mean;
        s_stats[1] = rsqrtf(var + 1e-5f);
    }
    __syncthreads();
    const float mean = s_stats[0], rstd = s_stats[1];

    for (int i = t * 4; i < 32768; i += 1024) {
        const int c = (g << 3) + (i >> 12);
        const float a = sc[c] * rstd;
        const float b2 = bi[c] - mean * a;
        float4 v = *(const float4*)&in[base + i];
        float4 o;
        o.x = v.x * a + b2; o.y = v.y * a + b2;
        o.z = v.z * a + b2; o.w = v.w * a + b2;
        if (do_silu) {
            o.x = o.x / (1.f + __expf(-o.x));
            o.y = o.y / (1.f + __expf(-o.y));
            o.z = o.z / (1.f + __expf(-o.z));
            o.w = o.w / (1.f + __expf(-o.w));
        }
        if (do_round) {
            o.x = tf32r(o.x); o.y = tf32r(o.y);
            o.z = tf32r(o.z); o.w = tf32r(o.w);
        }
        *(float4*)&out[base + i] = o;
    }
}

// ---------------------------------------------------------------------------
// time-MLP
// ---------------------------------------------------------------------------
__global__ __launch_bounds__(256) void mlp_kernel(
    const float* __restrict__ te, const float* __restrict__ w,
    const float* __restrict__ mb, float* __restrict__ temb)
{
    __shared__ float s[TDIM];
    const int b = blockIdx.x, t = threadIdx.x;
    for (int i = t; i < TDIM; i += 256) {
        float v = te[b * TDIM + i];
        s[i] = v / (1.f + __expf(-v));
    }
    __syncthreads();
    float acc = 0.f;
    for (int k = 0; k < TDIM; k++) acc = fmaf(s[k], w[k * CDIM + t], acc);
    temb[b * CDIM + t] = acc + mb[t];
}

// ---------------------------------------------------------------------------
// Launch
// ---------------------------------------------------------------------------
extern "C" void kernel_launch(void* const* d_in, const int* in_sizes, int n_in,
                              void* d_out, int out_size)
{
    const float* x        = (const float*)d_in[0];
    const float* time_emb = (const float*)d_in[1];
    const float* gn1_s    = (const float*)d_in[2];
    const float* gn1_b    = (const float*)d_in[3];
    const float* conv1_w  = (const float*)d_in[4];
    const float* conv1_b  = (const float*)d_in[5];
    const float* mlp_w    = (const float*)d_in[6];
    const float* mlp_b    = (const float*)d_in[7];
    const float* gn2_s    = (const float*)d_in[8];
    const float* gn2_b    = (const float*)d_in[9];
    const float* conv2_w  = (const float*)d_in[10];
    const float* conv2_b  = (const float*)d_in[11];
    const float* an_s     = (const float*)d_in[12];
    const float* an_b     = (const float*)d_in[13];
    const float* qkv_w    = (const float*)d_in[14];
    const float* qkv_b    = (const float*)d_in[15];
    const float* out_w    = (const float*)d_in[16];
    const float* out_b    = (const float*)d_in[17];
    float* out = (float*)d_out;

    float *bufA, *bufB, *temb, *w1p, *w2p, *wqr, *wor;
    __nv_bfloat16 *qT, *kT, *vbf;
    cudaGetSymbolAddress((void**)&bufA, g_bufA);
    cudaGetSymbolAddress((void**)&bufB, g_bufB);
    cudaGetSymbolAddress((void**)&temb, g_temb);
    cudaGetSymbolAddress((void**)&w1p,  g_w1p);
    cudaGetSymbolAddress((void**)&w2p,  g_w2p);
    cudaGetSymbolAddress((void**)&wqr,  g_wqr);
    cudaGetSymbolAddress((void**)&wor,  g_wor);
    cudaGetSymbolAddress((void**)&qT,   g_qT);
    cudaGetSymbolAddress((void**)&kT,   g_kT);
    cudaGetSymbolAddress((void**)&vbf,  g_vbf);

    cudaFuncSetAttribute(tf32_conv_kernel,
                         cudaFuncAttributeMaxDynamicSharedMemorySize, CV_SMEM);
    cudaFuncSetAttribute(tf32_gemm_kernel,
                         cudaFuncAttributeMaxDynamicSharedMemorySize, TF_SMEM);
    cudaFuncSetAttribute(tf32_qkv_kernel,
                         cudaFuncAttributeMaxDynamicSharedMemorySize, TF_SMEM);
    cudaFuncSetAttribute(flash2_kernel,
                         cudaFuncAttributeMaxDynamicSharedMemorySize, FB_SMEM);

    const long sAct = (long)CDIM * HW;

    // weight prep
    permw_kernel<<<2304, 256>>>(conv1_w, w1p);
    permw_kernel<<<2304, 256>>>(conv2_w, w2p);
    tf32_round_kernel<<<192, 256>>>(qkv_w, wqr, 3 * CDIM * CDIM / 4);
    tf32_round_kernel<<<64, 256>>>(out_w, wor, CDIM * CDIM / 4);

    mlp_kernel<<<BATCH, 256>>>(time_emb, mlp_w, mlp_b, temb);

    // t1 = silu(gn1(x)) [tf32-rounded]
    groupnorm_kernel<<<BATCH * 32, 256>>>(x, bufA, gn1_s, gn1_b, 1, 1);
    // h1 = conv1(t1) + b + temb
    tf32_conv_kernel<<<dim3(32, 2, BATCH), 256, CV_SMEM>>>(
        w1p, bufA, bufB, sAct, sAct, conv1_b, temb, nullptr);
    // t2 = silu(gn2(h1)) [tf32-rounded]
    groupnorm_kernel<<<BATCH * 32, 256>>>(bufB, bufA, gn2_s, gn2_b, 1, 1);
    // xr = conv2(t2) + b + x
    tf32_conv_kernel<<<dim3(32, 2, BATCH), 256, CV_SMEM>>>(
        w2p, bufA, bufB, sAct, sAct, conv2_b, nullptr, x);
    // a = gn_an(xr) [tf32-rounded]
    groupnorm_kernel<<<BATCH * 32, 256>>>(bufB, bufA, an_s, an_b, 0, 1);
    // qkv -> qT/kT/vbf bf16 directly
    tf32_qkv_kernel<<<dim3(32, 6, BATCH), 256, TF_SMEM>>>(
        wqr, bufA, qT, kT, vbf, sAct, qkv_b);

    // FA2 fused attention: O (tf32-rounded, [C][HW]) -> bufA
    flash2_kernel<<<dim3(HW / 128, BATCH), 256, FB_SMEM>>>(qT, kT, vbf, bufA);

    // out = W_out @ O + out_b + xr
    tf32_gemm_kernel<<<dim3(32, 2, BATCH), 256, TF_SMEM>>>(
        wor, bufA, out, CDIM, CDIM, sAct, sAct, out_b, bufB);
}